// round 8
// baseline (speedup 1.0000x reference)
#include <cuda_runtime.h>
#include <cuda_bf16.h>

// ---------------- problem constants ----------------
#define N_NODES 20000
#define N_EDGES 160000
#define MEGA_NB 64
#define MID_NB 148

// ---------------- device scratch (static; no allocs) ----------------
__device__ __align__(16) float g_P[N_NODES * 320];   // P[n, s, o] (max 8*40 cols)
__device__ __align__(16) float g_R[N_NODES * 40];    // R[n, o]
__device__ __align__(16) float g_AGG1[N_NODES * 40];
__device__ __align__(16) float g_AGG2[N_NODES * 24];
__device__ __align__(16) float g_AGG3[N_NODES * 24];
__device__ int   g_deg[N_NODES];      // zeroed at end of k_mega (and zero at load)
__device__ int   g_cursor[N_NODES];
__device__ int   g_bsum[40];
__device__ __align__(8)  int2   g_srt[N_EDGES];        // (src, tgt) sorted by src
__device__ __align__(16) float4 g_eperm[N_EDGES * 2];  // e payload, src-sorted
__device__ float g_poolpart[MEGA_NB * 24];
__device__ __align__(16) float g_v1[256];
__device__ __align__(16) float g_v2[768];
__device__ __align__(16) float g_v3[512];
__device__ float g_v3r[64];
__device__ unsigned g_barS;    // scanAB barrier
__device__ unsigned g_barM1;   // n2e2 barrier
__device__ unsigned g_barM2;   // n3e3 barrier
__device__ unsigned g_barcnt;  // mega barrier

// ---------------- helpers ----------------
__device__ __forceinline__ void ffma2(unsigned long long& d, unsigned long long a,
                                      unsigned long long b) {
    asm("fma.rn.f32x2 %0, %1, %2, %0;" : "+l"(d) : "l"(a), "l"(b));
}
__device__ __forceinline__ unsigned long long packf2(float x) {
    unsigned long long r;
    asm("mov.b64 %0, {%1, %1};" : "=l"(r) : "f"(x));
    return r;
}
__device__ __forceinline__ float2 unpackf2(unsigned long long v) {
    float2 f;
    asm("mov.b64 {%0, %1}, %2;" : "=f"(f.x), "=f"(f.y) : "l"(v));
    return f;
}
// grid barrier: nb blocks, all resident; *cnt zeroed earlier in the stream.
__device__ __forceinline__ void gridbar(unsigned* cnt, int& epoch, int nb) {
    __threadfence();
    __syncthreads();
    epoch++;
    if (threadIdx.x == 0) {
        atomicAdd(cnt, 1u);
        unsigned target = (unsigned)epoch * (unsigned)nb;
        while (*((volatile unsigned*)cnt) < target) __nanosleep(20);
    }
    __syncthreads();
}

// ---------------- k1: node1 (blocks 0..394) || hist (blocks 395..1019) ----------------
// node1: cols [0,320) P, [320,360) R, [360,400) AGG1(+bias). g_deg must be zero on entry
// (guaranteed: zero-initialized at load; re-zeroed by k_mega each call).
__global__ __launch_bounds__(256) void k1_node1_hist(
    const float* __restrict__ xin,
    const float* __restrict__ We, const float* __restrict__ be,
    const float* __restrict__ root, const float* __restrict__ bias,
    const int2* __restrict__ ei)
{
    constexpr int FI = 16, FO = 40, CC = 5;
    constexpr int CC16 = CC * 16;
    __shared__ __align__(16) float Wsh[FI * CC16];
    __shared__ float bsh[FO];
    int t = threadIdx.x;
    int b = blockIdx.x;

    if (b >= 395) {   // histogram blocks
        int i = (b - 395) * 256 + t;
        if (i < N_EDGES) atomicAdd(&g_deg[ei[i].x], 1);
        return;
    }

    int bx = b % 79;        // node tile
    int by = b / 79;        // col chunk
    int cg0 = by * CC;
    int colbase = cg0 * 16;

    if (b == 0 && t == 0) { g_barS = 0u; g_barM1 = 0u; g_barM2 = 0u; g_barcnt = 0u; }

    for (int idx = t; idx < FI * CC16; idx += 256) {
        int f = idx / CC16, cl = idx % CC16;
        int c = colbase + cl;
        float w;
        if (c < 8 * FO) {
            int s = c / FO, o = c % FO;
            w = We[s * (FI * FO) + f * FO + o];
        } else if (c < 9 * FO) {
            int o = c - 8 * FO;
            w = be[f * FO + o];
        } else {
            int o = c - 9 * FO;
            w = root[f * FO + o];
        }
        Wsh[idx] = w;
    }
    for (int idx = t; idx < FO; idx += 256) bsh[idx] = bias[idx];
    __syncthreads();

    int node = bx * 256 + t;
    if (node >= N_NODES) return;

    float h[FI];
    const float4* hv = reinterpret_cast<const float4*>(xin + (size_t)node * FI);
#pragma unroll
    for (int f4 = 0; f4 < FI / 4; f4++) {
        float4 a = hv[f4];
        h[4*f4+0]=a.x; h[4*f4+1]=a.y; h[4*f4+2]=a.z; h[4*f4+3]=a.w;
    }

    const ulonglong2* Wv = reinterpret_cast<const ulonglong2*>(Wsh);
    float4* Pv = reinterpret_cast<float4*>(g_P) + (size_t)node * 80;
    float4* Rv = reinterpret_cast<float4*>(g_R) + (size_t)node * 10;
    float4* Av = reinterpret_cast<float4*>(g_AGG1) + (size_t)node * 10;

#pragma unroll
    for (int cg = 0; cg < CC; cg++) {
        unsigned long long acc[8];
#pragma unroll
        for (int k = 0; k < 8; k++) acc[k] = 0ull;
#pragma unroll
        for (int f = 0; f < FI; f++) {
            const ulonglong2* wrow = Wv + f * (CC * 4) + cg * 4;
            ulonglong2 wA = wrow[0], wB = wrow[1], wC = wrow[2], wD = wrow[3];
            unsigned long long ha = packf2(h[f]);
            ffma2(acc[0], ha, wA.x); ffma2(acc[1], ha, wA.y);
            ffma2(acc[2], ha, wB.x); ffma2(acc[3], ha, wB.y);
            ffma2(acc[4], ha, wC.x); ffma2(acc[5], ha, wC.y);
            ffma2(acc[6], ha, wD.x); ffma2(acc[7], ha, wD.y);
        }
#pragma unroll
        for (int q = 0; q < 4; q++) {
            int cb = (cg0 + cg) * 16 + q * 4;
            float2 a0 = unpackf2(acc[2*q]), a1 = unpackf2(acc[2*q+1]);
            float4 va = make_float4(a0.x, a0.y, a1.x, a1.y);
            if (cb < 8 * FO) {
                Pv[cb / 4] = va;
            } else if (cb < 9 * FO) {
                Rv[(cb - 8 * FO) / 4] = va;
            } else {
                int o = cb - 9 * FO;
                va.x += bsh[o]; va.y += bsh[o+1]; va.z += bsh[o+2]; va.w += bsh[o+3];
                Av[o / 4] = va;
            }
        }
    }
}

// ---------------- k2: fused two-level scan (40 blocks x 512, 1 gridbar) ----------------
__global__ __launch_bounds__(512) void k_scanAB()
{
    __shared__ int wred[16];
    __shared__ int bs[40];
    __shared__ int base;
    __shared__ int wsum[16];
    int t = threadIdx.x;
    int lane = t & 31, w = t >> 5;
    int b = blockIdx.x;
    int epoch = 0;

    int idx = b * 500 + t;
    int d = (t < 500 && idx < N_NODES) ? g_deg[idx] : 0;

    // phase A: block sum
    {
        int s = d;
#pragma unroll
        for (int off = 16; off >= 1; off >>= 1)
            s += __shfl_down_sync(0xffffffffu, s, off);
        if (lane == 0) wred[w] = s;
        __syncthreads();
        if (w == 0) {
            int v = (lane < 16) ? wred[lane] : 0;
#pragma unroll
            for (int off = 8; off >= 1; off >>= 1)
                v += __shfl_down_sync(0xffffffffu, v, off);
            if (lane == 0) g_bsum[b] = v;
        }
    }
    gridbar(&g_barS, epoch, 40);

    // phase B: block prefix + local exclusive scan -> g_cursor
    if (t < 40) bs[t] = g_bsum[t];
    __syncthreads();
    if (t == 0) {
        int s = 0;
#pragma unroll
        for (int i = 0; i < 40; i++) if (i < b) s += bs[i];
        base = s;
    }
    int sc = d;
#pragma unroll
    for (int off = 1; off < 32; off <<= 1) {
        int n = __shfl_up_sync(0xffffffffu, sc, off);
        if (lane >= off) sc += n;
    }
    if (lane == 31) wsum[w] = sc;
    __syncthreads();
    if (w == 0) {
        int v = (lane < 16) ? wsum[lane] : 0;
#pragma unroll
        for (int off = 1; off < 16; off <<= 1) {
            int n = __shfl_up_sync(0xffffffffu, v, off);
            if (lane >= off) v += n;
        }
        if (lane < 16) wsum[lane] = v;
    }
    __syncthreads();
    int wbase = (w == 0) ? 0 : wsum[w - 1];
    if (t < 500 && idx < N_NODES) g_cursor[idx] = base + wbase + sc - d;
}

// ---------------- k3: scatter ----------------
__global__ void k_scatter(const int2* __restrict__ ei, const float4* __restrict__ e4) {
    int i = blockIdx.x * blockDim.x + threadIdx.x;
    if (i < N_EDGES) {
        int2 st = ei[i];
        float4 a = e4[2 * i], b = e4[2 * i + 1];
        int p = atomicAdd(&g_cursor[st.x], 1);
        g_srt[p] = st;
        g_eperm[2 * p] = a;
        g_eperm[2 * p + 1] = b;
    }
}

// ---------------- k4: edge layer 1 (5 threads/edge) ----------------
__global__ __launch_bounds__(256) void k_edge1()
{
    constexpr int FO = 40, FO4 = 10, TPE = 5, CH = 2;
    int gid = blockIdx.x * 256 + threadIdx.x;
    int edge = gid / TPE;
    if (edge >= N_EDGES) return;
    int part = gid - edge * TPE;

    int2 st = g_srt[edge];
    float4 ea = g_eperm[2 * edge];
    float4 eb = g_eperm[2 * edge + 1];

    const float4* P = reinterpret_cast<const float4*>(g_P)
                      + (size_t)st.x * (8 * FO4) + part * CH;
    const float4* R = reinterpret_cast<const float4*>(g_R)
                      + (size_t)st.x * FO4 + part * CH;
    float* dst = g_AGG1 + (size_t)st.y * FO + part * CH * 4;

#pragma unroll
    for (int c = 0; c < CH; c++) {
        float4 m = R[c];
        float4 p;
#define ACC_TERM(ES, SI) { p = P[(SI) * FO4 + c]; \
        m.x += (ES) * p.x; m.y += (ES) * p.y; m.z += (ES) * p.z; m.w += (ES) * p.w; }
        ACC_TERM(ea.x, 0) ACC_TERM(ea.y, 1) ACC_TERM(ea.z, 2) ACC_TERM(ea.w, 3)
        ACC_TERM(eb.x, 4) ACC_TERM(eb.y, 5) ACC_TERM(eb.z, 6) ACC_TERM(eb.w, 7)
#undef ACC_TERM
        asm volatile("red.global.add.v4.f32 [%0], {%1,%2,%3,%4};"
                     :: "l"(dst + c * 4), "f"(m.x), "f"(m.y), "f"(m.z), "f"(m.w)
                     : "memory");
    }
}

// ---------------- node phase (FO=24) for fused mid kernels ----------------
// item = node*3 + chunk; chunk covers 80 cols. COLS=240 staged in Wsh + bs[24].
template <int FI>
__device__ __forceinline__ void node_phase24(
    const float* __restrict__ hin, float* __restrict__ AGG,
    const float* __restrict__ Wsh, const float* __restrict__ bs, int item)
{
    constexpr int FO = 24;
    int node = item / 3;
    int chunk = item % 3;
    int cg0 = chunk * 5;

    float h[FI];
    const float4* hv = reinterpret_cast<const float4*>(hin + (size_t)node * FI);
#pragma unroll
    for (int f4 = 0; f4 < FI / 4; f4++) {
        float4 a = hv[f4];
        a.x = fmaxf(a.x, 0.f); a.y = fmaxf(a.y, 0.f);
        a.z = fmaxf(a.z, 0.f); a.w = fmaxf(a.w, 0.f);
        h[4*f4+0]=a.x; h[4*f4+1]=a.y; h[4*f4+2]=a.z; h[4*f4+3]=a.w;
    }

    const ulonglong2* Wv = reinterpret_cast<const ulonglong2*>(Wsh);
    float4* Pv = reinterpret_cast<float4*>(g_P) + (size_t)node * 48;
    float4* Rv = reinterpret_cast<float4*>(g_R) + (size_t)node * 6;
    float4* Av = reinterpret_cast<float4*>(AGG) + (size_t)node * 6;

#pragma unroll
    for (int cg = 0; cg < 5; cg++) {
        unsigned long long acc[8];
#pragma unroll
        for (int k = 0; k < 8; k++) acc[k] = 0ull;
#pragma unroll
        for (int f = 0; f < FI; f++) {
            const ulonglong2* wrow = Wv + f * 60 + (cg0 + cg) * 4;
            ulonglong2 wA = wrow[0], wB = wrow[1], wC = wrow[2], wD = wrow[3];
            unsigned long long ha = packf2(h[f]);
            ffma2(acc[0], ha, wA.x); ffma2(acc[1], ha, wA.y);
            ffma2(acc[2], ha, wB.x); ffma2(acc[3], ha, wB.y);
            ffma2(acc[4], ha, wC.x); ffma2(acc[5], ha, wC.y);
            ffma2(acc[6], ha, wD.x); ffma2(acc[7], ha, wD.y);
        }
#pragma unroll
        for (int q = 0; q < 4; q++) {
            int cb = (cg0 + cg) * 16 + q * 4;
            float2 a0 = unpackf2(acc[2*q]), a1 = unpackf2(acc[2*q+1]);
            float4 va = make_float4(a0.x, a0.y, a1.x, a1.y);
            if (cb < 8 * FO) {
                Pv[cb / 4] = va;
            } else if (cb < 9 * FO) {
                Rv[(cb - 8 * FO) / 4] = va;
            } else {
                int o = cb - 9 * FO;
                va.x += bs[o]; va.y += bs[o+1]; va.z += bs[o+2]; va.w += bs[o+3];
                Av[o / 4] = va;
            }
        }
    }
}

// edge phase FO=24, 3 thread-slots/edge, strided over persistent grid
__device__ __forceinline__ void edge_phase24(float* __restrict__ AGG,
                                             int start, int stride)
{
    constexpr int FO = 24, FO4 = 6, CH = 2;
    for (int gid = start; gid < 3 * N_EDGES; gid += stride) {
        int edge = gid / 3;
        int part = gid - edge * 3;
        int2 st = g_srt[edge];
        float4 ea = g_eperm[2 * edge];
        float4 eb = g_eperm[2 * edge + 1];
        const float4* P = reinterpret_cast<const float4*>(g_P)
                          + (size_t)st.x * 48 + part * CH;
        const float4* R = reinterpret_cast<const float4*>(g_R)
                          + (size_t)st.x * FO4 + part * CH;
        float* dst = AGG + (size_t)st.y * FO + part * CH * 4;
#pragma unroll
        for (int c = 0; c < CH; c++) {
            float4 m = R[c];
            float4 p;
#define ACC_TERM(ES, SI) { p = P[(SI) * FO4 + c]; \
            m.x += (ES) * p.x; m.y += (ES) * p.y; m.z += (ES) * p.z; m.w += (ES) * p.w; }
            ACC_TERM(ea.x, 0) ACC_TERM(ea.y, 1) ACC_TERM(ea.z, 2) ACC_TERM(ea.w, 3)
            ACC_TERM(eb.x, 4) ACC_TERM(eb.y, 5) ACC_TERM(eb.z, 6) ACC_TERM(eb.w, 7)
#undef ACC_TERM
            asm volatile("red.global.add.v4.f32 [%0], {%1,%2,%3,%4};"
                         :: "l"(dst + c * 4), "f"(m.x), "f"(m.y), "f"(m.z), "f"(m.w)
                         : "memory");
        }
    }
}

// ---------------- k5 / k6: fused node+edge layers (148 x 512, 1 gridbar) ----------------
template <int FI, int WHICH>   // WHICH=1: AGG1->AGG2 (bar M1); WHICH=2: AGG2->AGG3 (bar M2)
__global__ __launch_bounds__(512) void k_mid(
    const float* __restrict__ We, const float* __restrict__ be,
    const float* __restrict__ root, const float* __restrict__ bias)
{
    __shared__ __align__(16) float Wsh[FI * 240];
    __shared__ float bs[24];
    int t = threadIdx.x;
    int b = blockIdx.x;
    int epoch = 0;

    for (int idx = t; idx < FI * 240; idx += 512) {
        int f = idx / 240, c = idx % 240;
        float wv;
        if (c < 192)      wv = We[(c / 24) * (FI * 24) + f * 24 + (c % 24)];
        else if (c < 216) wv = be[f * 24 + (c - 192)];
        else              wv = root[f * 24 + (c - 216)];
        Wsh[idx] = wv;
    }
    if (t < 24) bs[t] = bias[t];
    __syncthreads();

    const float* hin = (WHICH == 1) ? g_AGG1 : g_AGG2;
    float* AGG       = (WHICH == 1) ? g_AGG2 : g_AGG3;

    int item = b * 512 + t;
    if (item < N_NODES * 3)
        node_phase24<FI>(hin, AGG, Wsh, bs, item);

    gridbar((WHICH == 1) ? &g_barM1 : &g_barM2, epoch, MID_NB);

    edge_phase24(AGG, b * 512 + t, MID_NB * 512);
}

// ---------------- k7: mega (pool + MLP; also re-zeroes g_deg for next call) ----------------
__global__ __launch_bounds__(512) void k_mega(
    const float* __restrict__ Wd1, const float* __restrict__ bd1,
    const float* __restrict__ Wd2, const float* __restrict__ bd2,
    const float* __restrict__ Wd3, const float* __restrict__ bd3,
    const float* __restrict__ Wd4, const float* __restrict__ bd4,
    const float* __restrict__ Wd5, const float* __restrict__ bd5,
    const float* __restrict__ Wd6, const float* __restrict__ bd6,
    float* __restrict__ out)
{
    __shared__ float w3s[256 * 12];
    __shared__ float w4s[768 * 8];
    __shared__ float w5s[512];
    __shared__ float a2[256];
    __shared__ float a3[768];
    __shared__ float v0[24];
    __shared__ float a1[96];
    __shared__ float poolacc[21][24];
    __shared__ float bd3s[12], bd4s[8];
    __shared__ float red8[8];

    int t = threadIdx.x;
    int b = blockIdx.x;
    int epoch = 0;

    // zero g_deg for the next launch (it is only used before this kernel)
    for (int i = b * 512 + t; i < N_NODES; i += MEGA_NB * 512) g_deg[i] = 0;

    for (int idx = t; idx < 256 * 12; idx += 512) {
        int i = idx / 12, j = idx % 12;
        w3s[idx] = Wd3[i * 768 + b * 12 + j];
    }
    for (int idx = t; idx < 768 * 8; idx += 512) {
        int i = idx / 8, j = idx % 8;
        w4s[idx] = Wd4[i * 512 + b * 8 + j];
    }
    if (t < 512) w5s[t] = Wd5[t * 64 + b];
    if (t < 12) bd3s[t] = bd3[b * 12 + t];
    if (t < 8)  bd4s[t] = bd4[b * 8 + t];
    float bd5b = bd5[b];
    float wd6b = Wd6[b];

    // phase P: pool partials (21 row-slots per block)
    {
        int c = t % 24, slot = t / 24;
        if (slot < 21) {
            float local = 0.0f;
            for (int r = b * 21 + slot; r < N_NODES; r += MEGA_NB * 21)
                local += fmaxf(__ldcg(&g_AGG3[r * 24 + c]), 0.0f);
            poolacc[slot][c] = local;
        }
        __syncthreads();
        if (t < 24) {
            float s = 0.0f;
#pragma unroll
            for (int k = 0; k < 21; k++) s += poolacc[k][t];
            g_poolpart[b * 24 + t] = s;
        }
    }
    gridbar(&g_barcnt, epoch, MEGA_NB);   // 1

    // phase A: block 0 does L1 (24->96) + L2 (96->256)
    if (b == 0) {
        if (t < 24) {
            float s = 0.0f;
            for (int k = 0; k < MEGA_NB; k++) s += __ldcg(&g_poolpart[k * 24 + t]);
            v0[t] = s;
        }
        __syncthreads();
        if (t < 96) {
            float acc = bd1[t];
#pragma unroll
            for (int i = 0; i < 24; i++) acc += v0[i] * Wd1[i * 96 + t];
            a1[t] = fmaxf(acc, 0.0f);
        }
        __syncthreads();
        if (t < 256) {
            float acc = bd2[t];
#pragma unroll 8
            for (int i = 0; i < 96; i++) acc += a1[i] * Wd2[i * 256 + t];
            g_v1[t] = fmaxf(acc, 0.0f);
        }
    }
    gridbar(&g_barcnt, epoch, MEGA_NB);   // 2

    // phase B: L3 256->768, 12 outputs per block
    if (t < 256) a2[t] = __ldcg(&g_v1[t]);
    __syncthreads();
    if (t < 192) {
        int jj = t >> 4, kk = t & 15;
        float acc = 0.0f;
#pragma unroll
        for (int r = 0; r < 16; r++) {
            int i = kk + 16 * r;
            acc += a2[i] * w3s[i * 12 + jj];
        }
#pragma unroll
        for (int off = 8; off >= 1; off >>= 1)
            acc += __shfl_down_sync(0xffffffffu, acc, off, 16);
        if (kk == 0) g_v2[b * 12 + jj] = fmaxf(acc + bd3s[jj], 0.0f);
    }
    gridbar(&g_barcnt, epoch, MEGA_NB);   // 3

    // phase C: L4 768->512, 8 outputs per block
    if (t < 256) {
#pragma unroll
        for (int k = 0; k < 3; k++) a3[t + k * 256] = __ldcg(&g_v2[t + k * 256]);
    }
    __syncthreads();
    if (t < 256) {
        int w = t >> 5, l = t & 31;
        float acc = 0.0f;
#pragma unroll
        for (int k = 0; k < 24; k++) {
            int i = l + 32 * k;
            acc += a3[i] * w4s[i * 8 + w];
        }
#pragma unroll
        for (int off = 16; off >= 1; off >>= 1)
            acc += __shfl_down_sync(0xffffffffu, acc, off);
        if (l == 0) g_v3[b * 8 + w] = fmaxf(acc + bd4s[w], 0.0f);
    }
    gridbar(&g_barcnt, epoch, MEGA_NB);   // 4

    // phase D: L5 512->64 (output b) * W6[b]
    if (t < 256) {
        float acc = __ldcg(&g_v3[t]) * w5s[t] + __ldcg(&g_v3[t + 256]) * w5s[t + 256];
#pragma unroll
        for (int off = 16; off >= 1; off >>= 1)
            acc += __shfl_down_sync(0xffffffffu, acc, off);
        int w = t >> 5, l = t & 31;
        if (l == 0) red8[w] = acc;
    }
    __syncthreads();
    if (t == 0) {
        float s = 0.0f;
#pragma unroll
        for (int k = 0; k < 8; k++) s += red8[k];
        g_v3r[b] = fmaxf(s + bd5b, 0.0f) * wd6b;
    }
    gridbar(&g_barcnt, epoch, MEGA_NB);   // 5

    // phase E: block 0 final
    if (b == 0 && t == 0) {
        float s = bd6[0];
#pragma unroll
        for (int k = 0; k < 64; k++) s += __ldcg(&g_v3r[k]);
        out[0] = s;
    }
}

// ---------------- launcher ----------------
extern "C" void kernel_launch(void* const* d_in, const int* in_sizes, int n_in,
                              void* d_out, int out_size)
{
    const float* x    = (const float*)d_in[0];
    const int*   ei   = (const int*)d_in[1];
    const float* e    = (const float*)d_in[2];
    const float* We1  = (const float*)d_in[3];
    const float* be1  = (const float*)d_in[4];
    const float* root1= (const float*)d_in[5];
    const float* b1   = (const float*)d_in[6];
    const float* We2  = (const float*)d_in[7];
    const float* be2  = (const float*)d_in[8];
    const float* root2= (const float*)d_in[9];
    const float* b2   = (const float*)d_in[10];
    const float* We3  = (const float*)d_in[11];
    const float* be3  = (const float*)d_in[12];
    const float* root3= (const float*)d_in[13];
    const float* b3   = (const float*)d_in[14];
    const float* Wd1  = (const float*)d_in[15];
    const float* bd1  = (const float*)d_in[16];
    const float* Wd2  = (const float*)d_in[17];
    const float* bd2  = (const float*)d_in[18];
    const float* Wd3  = (const float*)d_in[19];
    const float* bd3  = (const float*)d_in[20];
    const float* Wd4  = (const float*)d_in[21];
    const float* bd4  = (const float*)d_in[22];
    const float* Wd5  = (const float*)d_in[23];
    const float* bd5  = (const float*)d_in[24];
    const float* Wd6  = (const float*)d_in[25];
    const float* bd6  = (const float*)d_in[26];

    const int2* ei2 = (const int2*)ei;
    const float4* e4 = (const float4*)e;

    k1_node1_hist<<<395 + 625, 256>>>(x, We1, be1, root1, b1, ei2);
    k_scanAB<<<40, 512>>>();
    k_scatter<<<625, 256>>>(ei2, e4);
    k_edge1<<<(5 * N_EDGES + 255) / 256, 256>>>();
    k_mid<40, 1><<<MID_NB, 512>>>(We2, be2, root2, b2);
    k_mid<24, 2><<<MID_NB, 512>>>(We3, be3, root3, b3);
    k_mega<<<MEGA_NB, 512>>>(Wd1, bd1, Wd2, bd2, Wd3, bd3, Wd4, bd4, Wd5, bd5,
                             Wd6, bd6, (float*)d_out);
}

// round 9
// speedup vs baseline: 1.4449x; 1.4449x over previous
#include <cuda_runtime.h>
#include <cuda_bf16.h>

// ---------------- problem constants ----------------
#define N_NODES 20000
#define N_EDGES 160000
#define MEGA_NB 64

// ---------------- device scratch (static; no allocs) ----------------
__device__ __align__(16) float g_P[N_NODES * 320];   // P[n, s, o] (max 8*40 cols)
__device__ __align__(16) float g_R[N_NODES * 40];    // R[n, o]
__device__ __align__(16) float g_AGG1[N_NODES * 40];
__device__ __align__(16) float g_AGG2[N_NODES * 24];
__device__ __align__(16) float g_AGG3[N_NODES * 24];
__device__ int   g_deg[N_NODES];
__device__ int   g_cursor[N_NODES];
__device__ int   g_bsum[40];
__device__ __align__(8)  int2   g_srt[N_EDGES];        // (src, tgt) sorted by src
__device__ __align__(16) float4 g_eperm[N_EDGES * 2];  // e payload, src-sorted
__device__ float g_poolpart[MEGA_NB * 24];
__device__ __align__(16) float g_v1[256];
__device__ __align__(16) float g_v2[768];
__device__ __align__(16) float g_v3[512];
__device__ float g_v3r[64];
__device__ unsigned g_barS;    // k_csr barrier
__device__ unsigned g_barcnt;  // mega barrier

// ---------------- helpers ----------------
__device__ __forceinline__ void ffma2(unsigned long long& d, unsigned long long a,
                                      unsigned long long b) {
    asm("fma.rn.f32x2 %0, %1, %2, %0;" : "+l"(d) : "l"(a), "l"(b));
}
__device__ __forceinline__ unsigned long long packf2(float x) {
    unsigned long long r;
    asm("mov.b64 %0, {%1, %1};" : "=l"(r) : "f"(x));
    return r;
}
__device__ __forceinline__ float2 unpackf2(unsigned long long v) {
    float2 f;
    asm("mov.b64 {%0, %1}, %2;" : "=f"(f.x), "=f"(f.y) : "l"(v));
    return f;
}
// grid barrier: nb blocks, all resident; *cnt zeroed earlier in the stream.
__device__ __forceinline__ void gridbar(unsigned* cnt, int& epoch, int nb) {
    __threadfence();
    __syncthreads();
    epoch++;
    if (threadIdx.x == 0) {
        atomicAdd(cnt, 1u);
        unsigned target = (unsigned)epoch * (unsigned)nb;
        while (*((volatile unsigned*)cnt) < target) __nanosleep(20);
    }
    __syncthreads();
}

// ---------------- node kernel ----------------
// grid (node-tiles, col-chunks); 256 thr, 1 node/thread, f32x2 math.
// cols [0,8FO): P   [8FO,9FO): R   [9FO,10FO): AGG(+bias)
// ZERO=1 (layer1): blockIdx.y==0 blocks also zero g_deg / barrier counters.
template <int LAYER, int FI, int FO, int CC, int ZERO>
__global__ __launch_bounds__(256) void k_node(
    const float* __restrict__ xin,
    const float* __restrict__ We, const float* __restrict__ be,
    const float* __restrict__ root, const float* __restrict__ bias)
{
    constexpr int CC16 = CC * 16;
    __shared__ __align__(16) float Wsh[FI * CC16];
    __shared__ float bsh[FO];
    int t = threadIdx.x;
    int cg0 = blockIdx.y * CC;
    int colbase = cg0 * 16;

    if (ZERO) {
        if (blockIdx.y == 0) {
            int n = blockIdx.x * 256 + t;
            if (n < N_NODES) g_deg[n] = 0;
            if (blockIdx.x == 0 && t == 0) { g_barcnt = 0u; g_barS = 0u; }
        }
    }

    for (int idx = t; idx < FI * CC16; idx += 256) {
        int f = idx / CC16, cl = idx % CC16;
        int c = colbase + cl;
        float w;
        if (c < 8 * FO) {
            int s = c / FO, o = c % FO;
            w = We[s * (FI * FO) + f * FO + o];
        } else if (c < 9 * FO) {
            int o = c - 8 * FO;
            w = be[f * FO + o];
        } else {
            int o = c - 9 * FO;
            w = root[f * FO + o];
        }
        Wsh[idx] = w;
    }
    for (int idx = t; idx < FO; idx += 256) bsh[idx] = bias[idx];
    __syncthreads();

    int node = blockIdx.x * 256 + t;
    if (node >= N_NODES) return;

    const float* hin;
    if (LAYER == 1)      hin = xin;
    else if (LAYER == 2) hin = g_AGG1;
    else                 hin = g_AGG2;
    float* AGG;
    if (LAYER == 1)      AGG = g_AGG1;
    else if (LAYER == 2) AGG = g_AGG2;
    else                 AGG = g_AGG3;

    float h[FI];
    const float4* hv = reinterpret_cast<const float4*>(hin + (size_t)node * FI);
#pragma unroll
    for (int f4 = 0; f4 < FI / 4; f4++) {
        float4 a = hv[f4];
        if (LAYER != 1) {
            a.x = fmaxf(a.x, 0.f); a.y = fmaxf(a.y, 0.f);
            a.z = fmaxf(a.z, 0.f); a.w = fmaxf(a.w, 0.f);
        }
        h[4*f4+0]=a.x; h[4*f4+1]=a.y; h[4*f4+2]=a.z; h[4*f4+3]=a.w;
    }

    const ulonglong2* Wv = reinterpret_cast<const ulonglong2*>(Wsh);
    float4* Pv = reinterpret_cast<float4*>(g_P) + (size_t)node * (8 * FO / 4);
    float4* Rv = reinterpret_cast<float4*>(g_R) + (size_t)node * (FO / 4);
    float4* Av = reinterpret_cast<float4*>(AGG) + (size_t)node * (FO / 4);

#pragma unroll
    for (int cg = 0; cg < CC; cg++) {
        unsigned long long acc[8];
#pragma unroll
        for (int k = 0; k < 8; k++) acc[k] = 0ull;
#pragma unroll
        for (int f = 0; f < FI; f++) {
            const ulonglong2* wrow = Wv + f * (CC * 4) + cg * 4;
            ulonglong2 wA = wrow[0], wB = wrow[1], wC = wrow[2], wD = wrow[3];
            unsigned long long ha = packf2(h[f]);
            ffma2(acc[0], ha, wA.x); ffma2(acc[1], ha, wA.y);
            ffma2(acc[2], ha, wB.x); ffma2(acc[3], ha, wB.y);
            ffma2(acc[4], ha, wC.x); ffma2(acc[5], ha, wC.y);
            ffma2(acc[6], ha, wD.x); ffma2(acc[7], ha, wD.y);
        }
#pragma unroll
        for (int q = 0; q < 4; q++) {
            int cb = (cg0 + cg) * 16 + q * 4;
            float2 a0 = unpackf2(acc[2*q]), a1 = unpackf2(acc[2*q+1]);
            float4 va = make_float4(a0.x, a0.y, a1.x, a1.y);
            if (cb < 8 * FO) {
                Pv[cb / 4] = va;
            } else if (cb < 9 * FO) {
                Rv[(cb - 8 * FO) / 4] = va;
            } else {
                int o = cb - 9 * FO;
                va.x += bsh[o]; va.y += bsh[o+1]; va.z += bsh[o+2]; va.w += bsh[o+3];
                Av[o / 4] = va;
            }
        }
    }
}

// ---------------- k_csr: hist + two-level scan (40 blocks x 512, 2 gridbars) ----------------
__global__ __launch_bounds__(512) void k_csr(const int2* __restrict__ ei)
{
    __shared__ int wred[16];
    __shared__ int bs[40];
    __shared__ int base;
    __shared__ int wsum[16];
    int t = threadIdx.x;
    int lane = t & 31, w = t >> 5;
    int b = blockIdx.x;
    int epoch = 0;

    // phase 0: histogram (fire-and-forget REDs; loads independent)
    for (int i = b * 512 + t; i < N_EDGES; i += 40 * 512)
        atomicAdd(&g_deg[ei[i].x], 1);
    gridbar(&g_barS, epoch, 40);

    int idx = b * 500 + t;
    int d = (t < 500 && idx < N_NODES) ? g_deg[idx] : 0;

    // phase A: block sum
    {
        int s = d;
#pragma unroll
        for (int off = 16; off >= 1; off >>= 1)
            s += __shfl_down_sync(0xffffffffu, s, off);
        if (lane == 0) wred[w] = s;
        __syncthreads();
        if (w == 0) {
            int v = (lane < 16) ? wred[lane] : 0;
#pragma unroll
            for (int off = 8; off >= 1; off >>= 1)
                v += __shfl_down_sync(0xffffffffu, v, off);
            if (lane == 0) g_bsum[b] = v;
        }
    }
    gridbar(&g_barS, epoch, 40);

    // phase B: block prefix + local exclusive scan -> g_cursor
    if (t < 40) bs[t] = g_bsum[t];
    __syncthreads();
    if (t == 0) {
        int s = 0;
#pragma unroll
        for (int i = 0; i < 40; i++) if (i < b) s += bs[i];
        base = s;
    }
    int sc = d;
#pragma unroll
    for (int off = 1; off < 32; off <<= 1) {
        int n = __shfl_up_sync(0xffffffffu, sc, off);
        if (lane >= off) sc += n;
    }
    if (lane == 31) wsum[w] = sc;
    __syncthreads();
    if (w == 0) {
        int v = (lane < 16) ? wsum[lane] : 0;
#pragma unroll
        for (int off = 1; off < 16; off <<= 1) {
            int n = __shfl_up_sync(0xffffffffu, v, off);
            if (lane >= off) v += n;
        }
        if (lane < 16) wsum[lane] = v;
    }
    __syncthreads();
    int wbase = (w == 0) ? 0 : wsum[w - 1];
    if (t < 500 && idx < N_NODES) g_cursor[idx] = base + wbase + sc - d;
}

// ---------------- scatter ----------------
__global__ void k_scatter(const int2* __restrict__ ei, const float4* __restrict__ e4) {
    int i = blockIdx.x * blockDim.x + threadIdx.x;
    if (i < N_EDGES) {
        int2 st = ei[i];
        float4 a = e4[2 * i], b = e4[2 * i + 1];
        int p = atomicAdd(&g_cursor[st.x], 1);
        g_srt[p] = st;
        g_eperm[2 * p] = a;
        g_eperm[2 * p + 1] = b;
    }
}

// ---------------- edge kernel ----------------
// TPE threads per edge, each handles FO4/TPE float4 column chunks.
template <int LAYER, int FO, int TPE>
__global__ __launch_bounds__(256) void k_edge()
{
    constexpr int FO4 = FO / 4;
    constexpr int CH = FO4 / TPE;   // chunks per thread
    int gid = blockIdx.x * 256 + threadIdx.x;
    int edge = gid / TPE;
    if (edge >= N_EDGES) return;
    int part = gid - edge * TPE;

    int2 st = g_srt[edge];
    float4 ea = g_eperm[2 * edge];
    float4 eb = g_eperm[2 * edge + 1];

    const float4* P = reinterpret_cast<const float4*>(g_P)
                      + (size_t)st.x * (8 * FO4) + part * CH;
    const float4* R = reinterpret_cast<const float4*>(g_R)
                      + (size_t)st.x * FO4 + part * CH;
    float* AGG;
    if (LAYER == 1)      AGG = g_AGG1;
    else if (LAYER == 2) AGG = g_AGG2;
    else                 AGG = g_AGG3;
    float* dst = AGG + (size_t)st.y * FO + part * CH * 4;

#pragma unroll
    for (int c = 0; c < CH; c++) {
        float4 m = R[c];
        float4 p;
#define ACC_TERM(ES, SI) { p = P[(SI) * FO4 + c]; \
        m.x += (ES) * p.x; m.y += (ES) * p.y; m.z += (ES) * p.z; m.w += (ES) * p.w; }
        ACC_TERM(ea.x, 0) ACC_TERM(ea.y, 1) ACC_TERM(ea.z, 2) ACC_TERM(ea.w, 3)
        ACC_TERM(eb.x, 4) ACC_TERM(eb.y, 5) ACC_TERM(eb.z, 6) ACC_TERM(eb.w, 7)
#undef ACC_TERM
        asm volatile("red.global.add.v4.f32 [%0], {%1,%2,%3,%4};"
                     :: "l"(dst + c * 4), "f"(m.x), "f"(m.y), "f"(m.z), "f"(m.w)
                     : "memory");
    }
}

// ---------------- mega kernel: pool + whole MLP (64 x 512) ----------------
__global__ __launch_bounds__(512) void k_mega(
    const float* __restrict__ Wd1, const float* __restrict__ bd1,
    const float* __restrict__ Wd2, const float* __restrict__ bd2,
    const float* __restrict__ Wd3, const float* __restrict__ bd3,
    const float* __restrict__ Wd4, const float* __restrict__ bd4,
    const float* __restrict__ Wd5, const float* __restrict__ bd5,
    const float* __restrict__ Wd6, const float* __restrict__ bd6,
    float* __restrict__ out)
{
    __shared__ float w3s[256 * 12];
    __shared__ float w4s[768 * 8];
    __shared__ float w5s[512];
    __shared__ float a2[256];
    __shared__ float a3[768];
    __shared__ float v0[24];
    __shared__ float a1[96];
    __shared__ float poolacc[21][24];
    __shared__ float bd3s[12], bd4s[8];
    __shared__ float red8[8];

    int t = threadIdx.x;
    int b = blockIdx.x;
    int epoch = 0;

    // weight staging (harness inputs)
    for (int idx = t; idx < 256 * 12; idx += 512) {
        int i = idx / 12, j = idx % 12;
        w3s[idx] = Wd3[i * 768 + b * 12 + j];
    }
    for (int idx = t; idx < 768 * 8; idx += 512) {
        int i = idx / 8, j = idx % 8;
        w4s[idx] = Wd4[i * 512 + b * 8 + j];
    }
    if (t < 512) w5s[t] = Wd5[t * 64 + b];
    if (t < 12) bd3s[t] = bd3[b * 12 + t];
    if (t < 8)  bd4s[t] = bd4[b * 8 + t];
    float bd5b = bd5[b];
    float wd6b = Wd6[b];

    // phase P: pool partials (21 row-slots per block)
    {
        int c = t % 24, slot = t / 24;
        if (slot < 21) {
            float local = 0.0f;
            for (int r = b * 21 + slot; r < N_NODES; r += MEGA_NB * 21)
                local += fmaxf(__ldcg(&g_AGG3[r * 24 + c]), 0.0f);
            poolacc[slot][c] = local;
        }
        __syncthreads();
        if (t < 24) {
            float s = 0.0f;
#pragma unroll
            for (int k = 0; k < 21; k++) s += poolacc[k][t];
            g_poolpart[b * 24 + t] = s;
        }
    }
    gridbar(&g_barcnt, epoch, MEGA_NB);   // 1

    // phase A: block 0 does L1 (24->96) + L2 (96->256)
    if (b == 0) {
        if (t < 24) {
            float s = 0.0f;
            for (int k = 0; k < MEGA_NB; k++) s += __ldcg(&g_poolpart[k * 24 + t]);
            v0[t] = s;
        }
        __syncthreads();
        if (t < 96) {
            float acc = bd1[t];
#pragma unroll
            for (int i = 0; i < 24; i++) acc += v0[i] * Wd1[i * 96 + t];
            a1[t] = fmaxf(acc, 0.0f);
        }
        __syncthreads();
        if (t < 256) {
            float acc = bd2[t];
#pragma unroll 8
            for (int i = 0; i < 96; i++) acc += a1[i] * Wd2[i * 256 + t];
            g_v1[t] = fmaxf(acc, 0.0f);
        }
    }
    gridbar(&g_barcnt, epoch, MEGA_NB);   // 2

    // phase B: L3 256->768, 12 outputs per block (16 threads each)
    if (t < 256) a2[t] = __ldcg(&g_v1[t]);
    __syncthreads();
    if (t < 192) {
        int jj = t >> 4, kk = t & 15;
        float acc = 0.0f;
#pragma unroll
        for (int r = 0; r < 16; r++) {
            int i = kk + 16 * r;
            acc += a2[i] * w3s[i * 12 + jj];
        }
#pragma unroll
        for (int off = 8; off >= 1; off >>= 1)
            acc += __shfl_down_sync(0xffffffffu, acc, off, 16);
        if (kk == 0) g_v2[b * 12 + jj] = fmaxf(acc + bd3s[jj], 0.0f);
    }
    gridbar(&g_barcnt, epoch, MEGA_NB);   // 3

    // phase C: L4 768->512, 8 outputs per block
    if (t < 256) {
#pragma unroll
        for (int k = 0; k < 3; k++) a3[t + k * 256] = __ldcg(&g_v2[t + k * 256]);
    }
    __syncthreads();
    if (t < 256) {
        int w = t >> 5, l = t & 31;
        float acc = 0.0f;
#pragma unroll
        for (int k = 0; k < 24; k++) {
            int i = l + 32 * k;
            acc += a3[i] * w4s[i * 8 + w];
        }
#pragma unroll
        for (int off = 16; off >= 1; off >>= 1)
            acc += __shfl_down_sync(0xffffffffu, acc, off);
        if (l == 0) g_v3[b * 8 + w] = fmaxf(acc + bd4s[w], 0.0f);
    }
    gridbar(&g_barcnt, epoch, MEGA_NB);   // 4

    // phase D: L5 512->64 (output b) * W6[b]
    if (t < 256) {
        float acc = __ldcg(&g_v3[t]) * w5s[t] + __ldcg(&g_v3[t + 256]) * w5s[t + 256];
#pragma unroll
        for (int off = 16; off >= 1; off >>= 1)
            acc += __shfl_down_sync(0xffffffffu, acc, off);
        int w = t >> 5, l = t & 31;
        if (l == 0) red8[w] = acc;
    }
    __syncthreads();
    if (t == 0) {
        float s = 0.0f;
#pragma unroll
        for (int k = 0; k < 8; k++) s += red8[k];
        g_v3r[b] = fmaxf(s + bd5b, 0.0f) * wd6b;
    }
    gridbar(&g_barcnt, epoch, MEGA_NB);   // 5

    // phase E: block 0 final
    if (b == 0 && t == 0) {
        float s = bd6[0];
#pragma unroll
        for (int k = 0; k < 64; k++) s += __ldcg(&g_v3r[k]);
        out[0] = s;
    }
}

// ---------------- launcher ----------------
extern "C" void kernel_launch(void* const* d_in, const int* in_sizes, int n_in,
                              void* d_out, int out_size)
{
    const float* x    = (const float*)d_in[0];
    const int*   ei   = (const int*)d_in[1];
    const float* e    = (const float*)d_in[2];
    const float* We1  = (const float*)d_in[3];
    const float* be1  = (const float*)d_in[4];
    const float* root1= (const float*)d_in[5];
    const float* b1   = (const float*)d_in[6];
    const float* We2  = (const float*)d_in[7];
    const float* be2  = (const float*)d_in[8];
    const float* root2= (const float*)d_in[9];
    const float* b2   = (const float*)d_in[10];
    const float* We3  = (const float*)d_in[11];
    const float* be3  = (const float*)d_in[12];
    const float* root3= (const float*)d_in[13];
    const float* b3   = (const float*)d_in[14];
    const float* Wd1  = (const float*)d_in[15];
    const float* bd1  = (const float*)d_in[16];
    const float* Wd2  = (const float*)d_in[17];
    const float* bd2  = (const float*)d_in[18];
    const float* Wd3  = (const float*)d_in[19];
    const float* bd3  = (const float*)d_in[20];
    const float* Wd4  = (const float*)d_in[21];
    const float* bd4  = (const float*)d_in[22];
    const float* Wd5  = (const float*)d_in[23];
    const float* bd5  = (const float*)d_in[24];
    const float* Wd6  = (const float*)d_in[25];
    const float* bd6  = (const float*)d_in[26];

    const int2* ei2 = (const int2*)ei;
    const float4* e4 = (const float4*)e;

    const int ntile = (N_NODES + 255) / 256;                 // 79
    const int flat_grid = (N_EDGES + 255) / 256;             // 625
    const int edge_grid40 = (5 * N_EDGES + 255) / 256;       // 3125
    const int edge_grid24 = (3 * N_EDGES + 255) / 256;       // 1875

    // node1 also zeroes g_deg / barrier counters (independent of CSR)
    k_node<1, 16, 40, 5, 1><<<dim3(ntile, 5), 256>>>(x, We1, be1, root1, b1);
    k_csr<<<40, 512>>>(ei2);
    k_scatter<<<flat_grid, 256>>>(ei2, e4);
    k_edge<1, 40, 5><<<edge_grid40, 256>>>();
    k_node<2, 40, 24, 5, 0><<<dim3(ntile, 3), 256>>>(nullptr, We2, be2, root2, b2);
    k_edge<2, 24, 3><<<edge_grid24, 256>>>();
    k_node<3, 24, 24, 5, 0><<<dim3(ntile, 3), 256>>>(nullptr, We3, be3, root3, b3);
    k_edge<3, 24, 3><<<edge_grid24, 256>>>();
    k_mega<<<MEGA_NB, 512>>>(Wd1, bd1, Wd2, bd2, Wd3, bd3, Wd4, bd4, Wd5, bd5,
                             Wd6, bd6, (float*)d_out);
}

// round 10
// speedup vs baseline: 1.5818x; 1.0947x over previous
#include <cuda_runtime.h>
#include <cuda_fp16.h>

// ---------------- problem constants ----------------
#define N_NODES 20000
#define N_EDGES 160000
#define MEGA_NB 64

// ---------------- device scratch (static; no allocs) ----------------
__device__ __align__(16) __half g_Ph[N_NODES * 320];  // P[n, s, o] fp16 (max 8*40 cols)
__device__ __align__(16) float g_R[N_NODES * 40];     // R[n, o] fp32
__device__ __align__(16) float g_AGG1[N_NODES * 40];
__device__ __align__(16) float g_AGG2[N_NODES * 24];
__device__ __align__(16) float g_AGG3[N_NODES * 24];
__device__ int   g_deg[N_NODES];
__device__ int   g_cursor[N_NODES];
__device__ int   g_bsum[40];
__device__ __align__(8)  int2   g_srt[N_EDGES];        // (src, tgt) sorted by src
__device__ __align__(16) float4 g_eperm[N_EDGES * 2];  // e payload, src-sorted
__device__ float g_poolpart[MEGA_NB * 24];
__device__ __align__(16) float g_v1[256];
__device__ __align__(16) float g_v2[768];
__device__ __align__(16) float g_v3[512];
__device__ float g_v3r[64];
__device__ unsigned g_barcnt;  // mega barrier

// ---------------- helpers ----------------
__device__ __forceinline__ void ffma2(unsigned long long& d, unsigned long long a,
                                      unsigned long long b) {
    asm("fma.rn.f32x2 %0, %1, %2, %0;" : "+l"(d) : "l"(a), "l"(b));
}
__device__ __forceinline__ unsigned long long packf2(float x) {
    unsigned long long r;
    asm("mov.b64 %0, {%1, %1};" : "=l"(r) : "f"(x));
    return r;
}
__device__ __forceinline__ float2 unpackf2(unsigned long long v) {
    float2 f;
    asm("mov.b64 {%0, %1}, %2;" : "=f"(f.x), "=f"(f.y) : "l"(v));
    return f;
}
__device__ __forceinline__ void gridbar(unsigned* cnt, int& epoch, int nb) {
    __threadfence();
    __syncthreads();
    epoch++;
    if (threadIdx.x == 0) {
        atomicAdd(cnt, 1u);
        unsigned target = (unsigned)epoch * (unsigned)nb;
        while (*((volatile unsigned*)cnt) < target) __nanosleep(20);
    }
    __syncthreads();
}

// ---------------- CSR build (separate kernels: max threads per phase) ----------------
__global__ void k_hist(const int2* __restrict__ ei) {
    int i = blockIdx.x * blockDim.x + threadIdx.x;
    if (i < N_EDGES) atomicAdd(&g_deg[ei[i].x], 1);
}

__global__ __launch_bounds__(512) void k_scanA() {
    __shared__ int wred[16];
    int t = threadIdx.x;
    int lane = t & 31, w = t >> 5;
    int idx = blockIdx.x * 500 + t;
    int d = (t < 500 && idx < N_NODES) ? g_deg[idx] : 0;
    int s = d;
#pragma unroll
    for (int off = 16; off >= 1; off >>= 1) s += __shfl_down_sync(0xffffffffu, s, off);
    if (lane == 0) wred[w] = s;
    __syncthreads();
    if (w == 0) {
        int v = (lane < 16) ? wred[lane] : 0;
#pragma unroll
        for (int off = 8; off >= 1; off >>= 1) v += __shfl_down_sync(0xffffffffu, v, off);
        if (lane == 0) g_bsum[blockIdx.x] = v;
    }
}

__global__ __launch_bounds__(512) void k_scanB() {
    __shared__ int bs[40];
    __shared__ int base;
    __shared__ int wsum[16];
    int t = threadIdx.x;
    int lane = t & 31, w = t >> 5;
    int b = blockIdx.x;
    if (t < 40) bs[t] = g_bsum[t];
    __syncthreads();
    if (t == 0) {
        int s = 0;
#pragma unroll
        for (int i = 0; i < 40; i++) if (i < b) s += bs[i];
        base = s;
    }
    int idx = b * 500 + t;
    int d = (t < 500 && idx < N_NODES) ? g_deg[idx] : 0;
    int sc = d;
#pragma unroll
    for (int off = 1; off < 32; off <<= 1) {
        int n = __shfl_up_sync(0xffffffffu, sc, off);
        if (lane >= off) sc += n;
    }
    if (lane == 31) wsum[w] = sc;
    __syncthreads();
    if (w == 0) {
        int v = (lane < 16) ? wsum[lane] : 0;
#pragma unroll
        for (int off = 1; off < 16; off <<= 1) {
            int n = __shfl_up_sync(0xffffffffu, v, off);
            if (lane >= off) v += n;
        }
        if (lane < 16) wsum[lane] = v;
    }
    __syncthreads();
    int wbase = (w == 0) ? 0 : wsum[w - 1];
    if (t < 500 && idx < N_NODES) g_cursor[idx] = base + wbase + sc - d;
}

__global__ void k_scatter(const int2* __restrict__ ei, const float4* __restrict__ e4) {
    int i = blockIdx.x * blockDim.x + threadIdx.x;
    if (i < N_EDGES) {
        int2 st = ei[i];
        float4 a = e4[2 * i], b = e4[2 * i + 1];
        int p = atomicAdd(&g_cursor[st.x], 1);
        g_srt[p] = st;
        g_eperm[2 * p] = a;
        g_eperm[2 * p + 1] = b;
    }
}

// ---------------- node kernel ----------------
// grid (node-tiles, col-chunks); 256 thr, 1 node/thread, f32x2 math.
// cols [0,8FO): P (stored fp16)   [8FO,9FO): R   [9FO,10FO): AGG(+bias)
template <int LAYER, int FI, int FO, int CC, int ZERO>
__global__ __launch_bounds__(256) void k_node(
    const float* __restrict__ xin,
    const float* __restrict__ We, const float* __restrict__ be,
    const float* __restrict__ root, const float* __restrict__ bias)
{
    constexpr int CC16 = CC * 16;
    __shared__ __align__(16) float Wsh[FI * CC16];
    __shared__ float bsh[FO];
    int t = threadIdx.x;
    int cg0 = blockIdx.y * CC;
    int colbase = cg0 * 16;

    if (ZERO) {
        if (blockIdx.y == 0) {
            int n = blockIdx.x * 256 + t;
            if (n < N_NODES) g_deg[n] = 0;
            if (blockIdx.x == 0 && t == 0) g_barcnt = 0u;
        }
    }

    for (int idx = t; idx < FI * CC16; idx += 256) {
        int f = idx / CC16, cl = idx % CC16;
        int c = colbase + cl;
        float w;
        if (c < 8 * FO) {
            int s = c / FO, o = c % FO;
            w = We[s * (FI * FO) + f * FO + o];
        } else if (c < 9 * FO) {
            int o = c - 8 * FO;
            w = be[f * FO + o];
        } else {
            int o = c - 9 * FO;
            w = root[f * FO + o];
        }
        Wsh[idx] = w;
    }
    for (int idx = t; idx < FO; idx += 256) bsh[idx] = bias[idx];
    __syncthreads();

    int node = blockIdx.x * 256 + t;
    if (node >= N_NODES) return;

    const float* hin;
    if (LAYER == 1)      hin = xin;
    else if (LAYER == 2) hin = g_AGG1;
    else                 hin = g_AGG2;
    float* AGG;
    if (LAYER == 1)      AGG = g_AGG1;
    else if (LAYER == 2) AGG = g_AGG2;
    else                 AGG = g_AGG3;

    float h[FI];
    const float4* hv = reinterpret_cast<const float4*>(hin + (size_t)node * FI);
#pragma unroll
    for (int f4 = 0; f4 < FI / 4; f4++) {
        float4 a = hv[f4];
        if (LAYER != 1) {
            a.x = fmaxf(a.x, 0.f); a.y = fmaxf(a.y, 0.f);
            a.z = fmaxf(a.z, 0.f); a.w = fmaxf(a.w, 0.f);
        }
        h[4*f4+0]=a.x; h[4*f4+1]=a.y; h[4*f4+2]=a.z; h[4*f4+3]=a.w;
    }

    const ulonglong2* Wv = reinterpret_cast<const ulonglong2*>(Wsh);
    // P row: 2*FO uint2 chunks (each 4 halves); R/AGG rows: FO/4 float4
    uint2* Pv = reinterpret_cast<uint2*>(g_Ph) + (size_t)node * (2 * FO);
    float4* Rv = reinterpret_cast<float4*>(g_R) + (size_t)node * (FO / 4);
    float4* Av = reinterpret_cast<float4*>(AGG) + (size_t)node * (FO / 4);

#pragma unroll
    for (int cg = 0; cg < CC; cg++) {
        unsigned long long acc[8];
#pragma unroll
        for (int k = 0; k < 8; k++) acc[k] = 0ull;
#pragma unroll
        for (int f = 0; f < FI; f++) {
            const ulonglong2* wrow = Wv + f * (CC * 4) + cg * 4;
            ulonglong2 wA = wrow[0], wB = wrow[1], wC = wrow[2], wD = wrow[3];
            unsigned long long ha = packf2(h[f]);
            ffma2(acc[0], ha, wA.x); ffma2(acc[1], ha, wA.y);
            ffma2(acc[2], ha, wB.x); ffma2(acc[3], ha, wB.y);
            ffma2(acc[4], ha, wC.x); ffma2(acc[5], ha, wC.y);
            ffma2(acc[6], ha, wD.x); ffma2(acc[7], ha, wD.y);
        }
#pragma unroll
        for (int q = 0; q < 4; q++) {
            int cb = (cg0 + cg) * 16 + q * 4;
            float2 a0 = unpackf2(acc[2*q]), a1 = unpackf2(acc[2*q+1]);
            float4 va = make_float4(a0.x, a0.y, a1.x, a1.y);
            if (cb < 8 * FO) {
                union { __half2 h2[2]; uint2 u; } pk;
                pk.h2[0] = __floats2half2_rn(va.x, va.y);
                pk.h2[1] = __floats2half2_rn(va.z, va.w);
                Pv[cb / 4] = pk.u;
            } else if (cb < 9 * FO) {
                Rv[(cb - 8 * FO) / 4] = va;
            } else {
                int o = cb - 9 * FO;
                va.x += bsh[o]; va.y += bsh[o+1]; va.z += bsh[o+2]; va.w += bsh[o+3];
                Av[o / 4] = va;
            }
        }
    }
}

// ---------------- edge kernel ----------------
// TPE threads per edge, each handles FO4/TPE column chunks (4 cols each).
// P loaded as fp16 (uint2 = 4 halves), converted to fp32 for math.
template <int LAYER, int FO, int TPE>
__global__ __launch_bounds__(256) void k_edge()
{
    constexpr int FO4 = FO / 4;
    constexpr int CH = FO4 / TPE;   // chunks per thread
    int gid = blockIdx.x * 256 + threadIdx.x;
    int edge = gid / TPE;
    if (edge >= N_EDGES) return;
    int part = gid - edge * TPE;

    int2 st = g_srt[edge];
    float4 ea = g_eperm[2 * edge];
    float4 eb = g_eperm[2 * edge + 1];

    const uint2* P = reinterpret_cast<const uint2*>(g_Ph)
                     + (size_t)st.x * (2 * FO) + part * CH;
    const float4* R = reinterpret_cast<const float4*>(g_R)
                      + (size_t)st.x * FO4 + part * CH;
    float* AGG;
    if (LAYER == 1)      AGG = g_AGG1;
    else if (LAYER == 2) AGG = g_AGG2;
    else                 AGG = g_AGG3;
    float* dst = AGG + (size_t)st.y * FO + part * CH * 4;

#pragma unroll
    for (int c = 0; c < CH; c++) {
        float4 m = R[c];
#define ACC_TERM(ES, SI) { \
        uint2 u = P[(SI) * FO4 + c]; \
        float2 f0 = __half22float2(*reinterpret_cast<__half2*>(&u.x)); \
        float2 f1 = __half22float2(*reinterpret_cast<__half2*>(&u.y)); \
        m.x += (ES) * f0.x; m.y += (ES) * f0.y; \
        m.z += (ES) * f1.x; m.w += (ES) * f1.y; }
        ACC_TERM(ea.x, 0) ACC_TERM(ea.y, 1) ACC_TERM(ea.z, 2) ACC_TERM(ea.w, 3)
        ACC_TERM(eb.x, 4) ACC_TERM(eb.y, 5) ACC_TERM(eb.z, 6) ACC_TERM(eb.w, 7)
#undef ACC_TERM
        asm volatile("red.global.add.v4.f32 [%0], {%1,%2,%3,%4};"
                     :: "l"(dst + c * 4), "f"(m.x), "f"(m.y), "f"(m.z), "f"(m.w)
                     : "memory");
    }
}

// ---------------- mega kernel: pool + whole MLP (64 x 512) ----------------
__global__ __launch_bounds__(512) void k_mega(
    const float* __restrict__ Wd1, const float* __restrict__ bd1,
    const float* __restrict__ Wd2, const float* __restrict__ bd2,
    const float* __restrict__ Wd3, const float* __restrict__ bd3,
    const float* __restrict__ Wd4, const float* __restrict__ bd4,
    const float* __restrict__ Wd5, const float* __restrict__ bd5,
    const float* __restrict__ Wd6, const float* __restrict__ bd6,
    float* __restrict__ out)
{
    __shared__ float w3s[256 * 12];
    __shared__ float w4s[768 * 8];
    __shared__ float w5s[512];
    __shared__ float a2[256];
    __shared__ float a3[768];
    __shared__ float v0[24];
    __shared__ float a1[96];
    __shared__ float poolacc[21][24];
    __shared__ float bd3s[12], bd4s[8];
    __shared__ float red8[8];

    int t = threadIdx.x;
    int b = blockIdx.x;
    int epoch = 0;

    for (int idx = t; idx < 256 * 12; idx += 512) {
        int i = idx / 12, j = idx % 12;
        w3s[idx] = Wd3[i * 768 + b * 12 + j];
    }
    for (int idx = t; idx < 768 * 8; idx += 512) {
        int i = idx / 8, j = idx % 8;
        w4s[idx] = Wd4[i * 512 + b * 8 + j];
    }
    if (t < 512) w5s[t] = Wd5[t * 64 + b];
    if (t < 12) bd3s[t] = bd3[b * 12 + t];
    if (t < 8)  bd4s[t] = bd4[b * 8 + t];
    float bd5b = bd5[b];
    float wd6b = Wd6[b];

    // phase P: pool partials (21 row-slots per block)
    {
        int c = t % 24, slot = t / 24;
        if (slot < 21) {
            float local = 0.0f;
            for (int r = b * 21 + slot; r < N_NODES; r += MEGA_NB * 21)
                local += fmaxf(__ldcg(&g_AGG3[r * 24 + c]), 0.0f);
            poolacc[slot][c] = local;
        }
        __syncthreads();
        if (t < 24) {
            float s = 0.0f;
#pragma unroll
            for (int k = 0; k < 21; k++) s += poolacc[k][t];
            g_poolpart[b * 24 + t] = s;
        }
    }
    gridbar(&g_barcnt, epoch, MEGA_NB);   // 1

    // phase A: block 0 does L1 (24->96) + L2 (96->256)
    if (b == 0) {
        if (t < 24) {
            float s = 0.0f;
            for (int k = 0; k < MEGA_NB; k++) s += __ldcg(&g_poolpart[k * 24 + t]);
            v0[t] = s;
        }
        __syncthreads();
        if (t < 96) {
            float acc = bd1[t];
#pragma unroll
            for (int i = 0; i < 24; i++) acc += v0[i] * Wd1[i * 96 + t];
            a1[t] = fmaxf(acc, 0.0f);
        }
        __syncthreads();
        if (t < 256) {
            float acc = bd2[t];
#pragma unroll 8
            for (int i = 0; i < 96; i++) acc += a1[i] * Wd2[i * 256 + t];
            g_v1[t] = fmaxf(acc, 0.0f);
        }
    }
    gridbar(&g_barcnt, epoch, MEGA_NB);   // 2

    // phase B: L3 256->768, 12 outputs per block (16 threads each)
    if (t < 256) a2[t] = __ldcg(&g_v1[t]);
    __syncthreads();
    if (t < 192) {
        int jj = t >> 4, kk = t & 15;
        float acc = 0.0f;
#pragma unroll
        for (int r = 0; r < 16; r++) {
            int i = kk + 16 * r;
            acc += a2[i] * w3s[i * 12 + jj];
        }
#pragma unroll
        for (int off = 8; off >= 1; off >>= 1)
            acc += __shfl_down_sync(0xffffffffu, acc, off, 16);
        if (kk == 0) g_v2[b * 12 + jj] = fmaxf(acc + bd3s[jj], 0.0f);
    }
    gridbar(&g_barcnt, epoch, MEGA_NB);   // 3

    // phase C: L4 768->512, 8 outputs per block
    if (t < 256) {
#pragma unroll
        for (int k = 0; k < 3; k++) a3[t + k * 256] = __ldcg(&g_v2[t + k * 256]);
    }
    __syncthreads();
    if (t < 256) {
        int w = t >> 5, l = t & 31;
        float acc = 0.0f;
#pragma unroll
        for (int k = 0; k < 24; k++) {
            int i = l + 32 * k;
            acc += a3[i] * w4s[i * 8 + w];
        }
#pragma unroll
        for (int off = 16; off >= 1; off >>= 1)
            acc += __shfl_down_sync(0xffffffffu, acc, off);
        if (l == 0) g_v3[b * 8 + w] = fmaxf(acc + bd4s[w], 0.0f);
    }
    gridbar(&g_barcnt, epoch, MEGA_NB);   // 4

    // phase D: L5 512->64 (output b) * W6[b]
    if (t < 256) {
        float acc = __ldcg(&g_v3[t]) * w5s[t] + __ldcg(&g_v3[t + 256]) * w5s[t + 256];
#pragma unroll
        for (int off = 16; off >= 1; off >>= 1)
            acc += __shfl_down_sync(0xffffffffu, acc, off);
        int w = t >> 5, l = t & 31;
        if (l == 0) red8[w] = acc;
    }
    __syncthreads();
    if (t == 0) {
        float s = 0.0f;
#pragma unroll
        for (int k = 0; k < 8; k++) s += red8[k];
        g_v3r[b] = fmaxf(s + bd5b, 0.0f) * wd6b;
    }
    gridbar(&g_barcnt, epoch, MEGA_NB);   // 5

    // phase E: block 0 final
    if (b == 0 && t == 0) {
        float s = bd6[0];
#pragma unroll
        for (int k = 0; k < 64; k++) s += __ldcg(&g_v3r[k]);
        out[0] = s;
    }
}

// ---------------- launcher ----------------
extern "C" void kernel_launch(void* const* d_in, const int* in_sizes, int n_in,
                              void* d_out, int out_size)
{
    const float* x    = (const float*)d_in[0];
    const int*   ei   = (const int*)d_in[1];
    const float* e    = (const float*)d_in[2];
    const float* We1  = (const float*)d_in[3];
    const float* be1  = (const float*)d_in[4];
    const float* root1= (const float*)d_in[5];
    const float* b1   = (const float*)d_in[6];
    const float* We2  = (const float*)d_in[7];
    const float* be2  = (const float*)d_in[8];
    const float* root2= (const float*)d_in[9];
    const float* b2   = (const float*)d_in[10];
    const float* We3  = (const float*)d_in[11];
    const float* be3  = (const float*)d_in[12];
    const float* root3= (const float*)d_in[13];
    const float* b3   = (const float*)d_in[14];
    const float* Wd1  = (const float*)d_in[15];
    const float* bd1  = (const float*)d_in[16];
    const float* Wd2  = (const float*)d_in[17];
    const float* bd2  = (const float*)d_in[18];
    const float* Wd3  = (const float*)d_in[19];
    const float* bd3  = (const float*)d_in[20];
    const float* Wd4  = (const float*)d_in[21];
    const float* bd4  = (const float*)d_in[22];
    const float* Wd5  = (const float*)d_in[23];
    const float* bd5  = (const float*)d_in[24];
    const float* Wd6  = (const float*)d_in[25];
    const float* bd6  = (const float*)d_in[26];

    const int2* ei2 = (const int2*)ei;
    const float4* e4 = (const float4*)e;

    const int ntile = (N_NODES + 255) / 256;                 // 79
    const int flat_grid = (N_EDGES + 255) / 256;             // 625
    const int edge_grid40 = (5 * N_EDGES + 255) / 256;       // 3125
    const int edge_grid24 = (3 * N_EDGES + 255) / 256;       // 1875

    // node1 also zeroes g_deg / barrier counter (independent of CSR)
    k_node<1, 16, 40, 5, 1><<<dim3(ntile, 5), 256>>>(x, We1, be1, root1, b1);
    k_hist<<<flat_grid, 256>>>(ei2);
    k_scanA<<<40, 512>>>();
    k_scanB<<<40, 512>>>();
    k_scatter<<<flat_grid, 256>>>(ei2, e4);
    k_edge<1, 40, 5><<<edge_grid40, 256>>>();
    k_node<2, 40, 24, 5, 0><<<dim3(ntile, 3), 256>>>(nullptr, We2, be2, root2, b2);
    k_edge<2, 24, 3><<<edge_grid24, 256>>>();
    k_node<3, 24, 24, 5, 0><<<dim3(ntile, 3), 256>>>(nullptr, We3, be3, root3, b3);
    k_edge<3, 24, 3><<<edge_grid24, 256>>>();
    k_mega<<<MEGA_NB, 512>>>(Wd1, bd1, Wd2, bd2, Wd3, bd3, Wd4, bd4, Wd5, bd5,
                             Wd6, bd6, (float*)d_out);
}

// round 11
// speedup vs baseline: 1.6333x; 1.0326x over previous
#include <cuda_runtime.h>
#include <cuda_fp16.h>

// ---------------- problem constants ----------------
#define N_NODES 20000
#define N_EDGES 160000
#define MEGA_NB 64

// ---------------- device scratch (static; no allocs) ----------------
__device__ __align__(16) __half g_Ph[N_NODES * 320];  // P[n, s, o] fp16 (max 8*40 cols)
__device__ __align__(16) float g_R[N_NODES * 40];     // R[n, o] fp32
__device__ __align__(16) float g_AGG1[N_NODES * 40];
__device__ __align__(16) float g_AGG2[N_NODES * 24];
__device__ __align__(16) float g_AGG3[N_NODES * 24];
__device__ int   g_deg[N_NODES];    // zero at load; re-zeroed by k_mega each call
__device__ int   g_cursor[N_NODES];
__device__ int   g_bsum[40];
__device__ __align__(8)  int2   g_srt[N_EDGES];        // (src, tgt) sorted by src
__device__ __align__(16) float4 g_eperm[N_EDGES * 2];  // e payload, src-sorted
__device__ float g_poolpart[MEGA_NB * 24];
__device__ __align__(16) float g_v1[256];
__device__ __align__(16) float g_v2[768];
__device__ __align__(16) float g_v3[512];
__device__ float g_v3r[64];
__device__ unsigned g_barS;    // scanAB barrier
__device__ unsigned g_barcnt;  // mega barrier

// ---------------- helpers ----------------
__device__ __forceinline__ void ffma2(unsigned long long& d, unsigned long long a,
                                      unsigned long long b) {
    asm("fma.rn.f32x2 %0, %1, %2, %0;" : "+l"(d) : "l"(a), "l"(b));
}
__device__ __forceinline__ unsigned long long packf2(float x) {
    unsigned long long r;
    asm("mov.b64 %0, {%1, %1};" : "=l"(r) : "f"(x));
    return r;
}
__device__ __forceinline__ float2 unpackf2(unsigned long long v) {
    float2 f;
    asm("mov.b64 {%0, %1}, %2;" : "=f"(f.x), "=f"(f.y) : "l"(v));
    return f;
}
__device__ __forceinline__ void gridbar(unsigned* cnt, int& epoch, int nb) {
    __threadfence();
    __syncthreads();
    epoch++;
    if (threadIdx.x == 0) {
        atomicAdd(cnt, 1u);
        unsigned target = (unsigned)epoch * (unsigned)nb;
        while (*((volatile unsigned*)cnt) < target) __nanosleep(20);
    }
    __syncthreads();
}

// ---------------- k1: node1 (blocks 0..394) || hist (blocks 395..1019) ----------------
// node1: cols [0,320) P(fp16), [320,360) R, [360,400) AGG1(+bias).
// g_deg is zero on entry (zero-init at load; re-zeroed by k_mega each call).
__global__ __launch_bounds__(256) void k1_node1_hist(
    const float* __restrict__ xin,
    const float* __restrict__ We, const float* __restrict__ be,
    const float* __restrict__ root, const float* __restrict__ bias,
    const int2* __restrict__ ei)
{
    constexpr int FI = 16, FO = 40, CC = 5;
    constexpr int CC16 = CC * 16;
    __shared__ __align__(16) float Wsh[FI * CC16];
    __shared__ float bsh[FO];
    int t = threadIdx.x;
    int b = blockIdx.x;

    if (b >= 395) {   // histogram blocks (full 160k-thread parallelism)
        int i = (b - 395) * 256 + t;
        if (i < N_EDGES) atomicAdd(&g_deg[ei[i].x], 1);
        return;
    }

    int bx = b % 79;        // node tile
    int by = b / 79;        // col chunk
    int cg0 = by * CC;
    int colbase = cg0 * 16;

    if (b == 0 && t == 0) { g_barS = 0u; g_barcnt = 0u; }  // no concurrent user

    for (int idx = t; idx < FI * CC16; idx += 256) {
        int f = idx / CC16, cl = idx % CC16;
        int c = colbase + cl;
        float w;
        if (c < 8 * FO) {
            int s = c / FO, o = c % FO;
            w = We[s * (FI * FO) + f * FO + o];
        } else if (c < 9 * FO) {
            int o = c - 8 * FO;
            w = be[f * FO + o];
        } else {
            int o = c - 9 * FO;
            w = root[f * FO + o];
        }
        Wsh[idx] = w;
    }
    for (int idx = t; idx < FO; idx += 256) bsh[idx] = bias[idx];
    __syncthreads();

    int node = bx * 256 + t;
    if (node >= N_NODES) return;

    float h[FI];
    const float4* hv = reinterpret_cast<const float4*>(xin + (size_t)node * FI);
#pragma unroll
    for (int f4 = 0; f4 < FI / 4; f4++) {
        float4 a = hv[f4];
        h[4*f4+0]=a.x; h[4*f4+1]=a.y; h[4*f4+2]=a.z; h[4*f4+3]=a.w;
    }

    const ulonglong2* Wv = reinterpret_cast<const ulonglong2*>(Wsh);
    uint2* Pv = reinterpret_cast<uint2*>(g_Ph) + (size_t)node * (2 * FO);
    float4* Rv = reinterpret_cast<float4*>(g_R) + (size_t)node * (FO / 4);
    float4* Av = reinterpret_cast<float4*>(g_AGG1) + (size_t)node * (FO / 4);

#pragma unroll
    for (int cg = 0; cg < CC; cg++) {
        unsigned long long acc[8];
#pragma unroll
        for (int k = 0; k < 8; k++) acc[k] = 0ull;
#pragma unroll
        for (int f = 0; f < FI; f++) {
            const ulonglong2* wrow = Wv + f * (CC * 4) + cg * 4;
            ulonglong2 wA = wrow[0], wB = wrow[1], wC = wrow[2], wD = wrow[3];
            unsigned long long ha = packf2(h[f]);
            ffma2(acc[0], ha, wA.x); ffma2(acc[1], ha, wA.y);
            ffma2(acc[2], ha, wB.x); ffma2(acc[3], ha, wB.y);
            ffma2(acc[4], ha, wC.x); ffma2(acc[5], ha, wC.y);
            ffma2(acc[6], ha, wD.x); ffma2(acc[7], ha, wD.y);
        }
#pragma unroll
        for (int q = 0; q < 4; q++) {
            int cb = (cg0 + cg) * 16 + q * 4;
            float2 a0 = unpackf2(acc[2*q]), a1 = unpackf2(acc[2*q+1]);
            float4 va = make_float4(a0.x, a0.y, a1.x, a1.y);
            if (cb < 8 * FO) {
                union { __half2 h2[2]; uint2 u; } pk;
                pk.h2[0] = __floats2half2_rn(va.x, va.y);
                pk.h2[1] = __floats2half2_rn(va.z, va.w);
                Pv[cb / 4] = pk.u;
            } else if (cb < 9 * FO) {
                Rv[(cb - 8 * FO) / 4] = va;
            } else {
                int o = cb - 9 * FO;
                va.x += bsh[o]; va.y += bsh[o+1]; va.z += bsh[o+2]; va.w += bsh[o+3];
                Av[o / 4] = va;
            }
        }
    }
}

// ---------------- k2: fused two-level scan (40 blocks x 512, 1 gridbar) ----------------
__global__ __launch_bounds__(512) void k_scanAB()
{
    __shared__ int wred[16];
    __shared__ int bs[40];
    __shared__ int base;
    __shared__ int wsum[16];
    int t = threadIdx.x;
    int lane = t & 31, w = t >> 5;
    int b = blockIdx.x;
    int epoch = 0;

    int idx = b * 500 + t;
    int d = (t < 500 && idx < N_NODES) ? g_deg[idx] : 0;

    // phase A: block sum
    {
        int s = d;
#pragma unroll
        for (int off = 16; off >= 1; off >>= 1)
            s += __shfl_down_sync(0xffffffffu, s, off);
        if (lane == 0) wred[w] = s;
        __syncthreads();
        if (w == 0) {
            int v = (lane < 16) ? wred[lane] : 0;
#pragma unroll
            for (int off = 8; off >= 1; off >>= 1)
                v += __shfl_down_sync(0xffffffffu, v, off);
            if (lane == 0) g_bsum[b] = v;
        }
    }
    gridbar(&g_barS, epoch, 40);

    // phase B: block prefix + local exclusive scan -> g_cursor
    if (t < 40) bs[t] = g_bsum[t];
    __syncthreads();
    if (t == 0) {
        int s = 0;
#pragma unroll
        for (int i = 0; i < 40; i++) if (i < b) s += bs[i];
        base = s;
    }
    int sc = d;
#pragma unroll
    for (int off = 1; off < 32; off <<= 1) {
        int n = __shfl_up_sync(0xffffffffu, sc, off);
        if (lane >= off) sc += n;
    }
    if (lane == 31) wsum[w] = sc;
    __syncthreads();
    if (w == 0) {
        int v = (lane < 16) ? wsum[lane] : 0;
#pragma unroll
        for (int off = 1; off < 16; off <<= 1) {
            int n = __shfl_up_sync(0xffffffffu, v, off);
            if (lane >= off) v += n;
        }
        if (lane < 16) wsum[lane] = v;
    }
    __syncthreads();
    int wbase = (w == 0) ? 0 : wsum[w - 1];
    if (t < 500 && idx < N_NODES) g_cursor[idx] = base + wbase + sc - d;
}

// ---------------- k3: scatter (1 edge/thread, max parallelism) ----------------
__global__ void k_scatter(const int2* __restrict__ ei, const float4* __restrict__ e4) {
    int i = blockIdx.x * blockDim.x + threadIdx.x;
    if (i < N_EDGES) {
        int2 st = ei[i];
        float4 a = e4[2 * i], b = e4[2 * i + 1];
        int p = atomicAdd(&g_cursor[st.x], 1);
        g_srt[p] = st;
        g_eperm[2 * p] = a;
        g_eperm[2 * p + 1] = b;
    }
}

// ---------------- node kernel (layers 2/3) ----------------
template <int LAYER, int FI, int FO, int CC>
__global__ __launch_bounds__(256) void k_node(
    const float* __restrict__ We, const float* __restrict__ be,
    const float* __restrict__ root, const float* __restrict__ bias)
{
    constexpr int CC16 = CC * 16;
    __shared__ __align__(16) float Wsh[FI * CC16];
    __shared__ float bsh[FO];
    int t = threadIdx.x;
    int cg0 = blockIdx.y * CC;
    int colbase = cg0 * 16;

    for (int idx = t; idx < FI * CC16; idx += 256) {
        int f = idx / CC16, cl = idx % CC16;
        int c = colbase + cl;
        float w;
        if (c < 8 * FO) {
            int s = c / FO, o = c % FO;
            w = We[s * (FI * FO) + f * FO + o];
        } else if (c < 9 * FO) {
            int o = c - 8 * FO;
            w = be[f * FO + o];
        } else {
            int o = c - 9 * FO;
            w = root[f * FO + o];
        }
        Wsh[idx] = w;
    }
    for (int idx = t; idx < FO; idx += 256) bsh[idx] = bias[idx];
    __syncthreads();

    int node = blockIdx.x * 256 + t;
    if (node >= N_NODES) return;

    const float* hin = (LAYER == 2) ? g_AGG1 : g_AGG2;
    float* AGG       = (LAYER == 2) ? g_AGG2 : g_AGG3;

    float h[FI];
    const float4* hv = reinterpret_cast<const float4*>(hin + (size_t)node * FI);
#pragma unroll
    for (int f4 = 0; f4 < FI / 4; f4++) {
        float4 a = hv[f4];
        a.x = fmaxf(a.x, 0.f); a.y = fmaxf(a.y, 0.f);
        a.z = fmaxf(a.z, 0.f); a.w = fmaxf(a.w, 0.f);
        h[4*f4+0]=a.x; h[4*f4+1]=a.y; h[4*f4+2]=a.z; h[4*f4+3]=a.w;
    }

    const ulonglong2* Wv = reinterpret_cast<const ulonglong2*>(Wsh);
    uint2* Pv = reinterpret_cast<uint2*>(g_Ph) + (size_t)node * (2 * FO);
    float4* Rv = reinterpret_cast<float4*>(g_R) + (size_t)node * (FO / 4);
    float4* Av = reinterpret_cast<float4*>(AGG) + (size_t)node * (FO / 4);

#pragma unroll
    for (int cg = 0; cg < CC; cg++) {
        unsigned long long acc[8];
#pragma unroll
        for (int k = 0; k < 8; k++) acc[k] = 0ull;
#pragma unroll
        for (int f = 0; f < FI; f++) {
            const ulonglong2* wrow = Wv + f * (CC * 4) + cg * 4;
            ulonglong2 wA = wrow[0], wB = wrow[1], wC = wrow[2], wD = wrow[3];
            unsigned long long ha = packf2(h[f]);
            ffma2(acc[0], ha, wA.x); ffma2(acc[1], ha, wA.y);
            ffma2(acc[2], ha, wB.x); ffma2(acc[3], ha, wB.y);
            ffma2(acc[4], ha, wC.x); ffma2(acc[5], ha, wC.y);
            ffma2(acc[6], ha, wD.x); ffma2(acc[7], ha, wD.y);
        }
#pragma unroll
        for (int q = 0; q < 4; q++) {
            int cb = (cg0 + cg) * 16 + q * 4;
            float2 a0 = unpackf2(acc[2*q]), a1 = unpackf2(acc[2*q+1]);
            float4 va = make_float4(a0.x, a0.y, a1.x, a1.y);
            if (cb < 8 * FO) {
                union { __half2 h2[2]; uint2 u; } pk;
                pk.h2[0] = __floats2half2_rn(va.x, va.y);
                pk.h2[1] = __floats2half2_rn(va.z, va.w);
                Pv[cb / 4] = pk.u;
            } else if (cb < 9 * FO) {
                Rv[(cb - 8 * FO) / 4] = va;
            } else {
                int o = cb - 9 * FO;
                va.x += bsh[o]; va.y += bsh[o+1]; va.z += bsh[o+2]; va.w += bsh[o+3];
                Av[o / 4] = va;
            }
        }
    }
}

// ---------------- edge kernel ----------------
// TPE threads per edge, each handles FO4/TPE column chunks (4 cols each).
// P loaded fp16 (uint2 = 4 halves), fp32 math, red.v4 scatter-add.
template <int LAYER, int FO, int TPE>
__global__ __launch_bounds__(256) void k_edge()
{
    constexpr int FO4 = FO / 4;
    constexpr int CH = FO4 / TPE;
    int gid = blockIdx.x * 256 + threadIdx.x;
    int edge = gid / TPE;
    if (edge >= N_EDGES) return;
    int part = gid - edge * TPE;

    int2 st = g_srt[edge];
    float4 ea = g_eperm[2 * edge];
    float4 eb = g_eperm[2 * edge + 1];

    const uint2* P = reinterpret_cast<const uint2*>(g_Ph)
                     + (size_t)st.x * (2 * FO) + part * CH;
    const float4* R = reinterpret_cast<const float4*>(g_R)
                      + (size_t)st.x * FO4 + part * CH;
    float* AGG;
    if (LAYER == 1)      AGG = g_AGG1;
    else if (LAYER == 2) AGG = g_AGG2;
    else                 AGG = g_AGG3;
    float* dst = AGG + (size_t)st.y * FO + part * CH * 4;

#pragma unroll
    for (int c = 0; c < CH; c++) {
        float4 m = R[c];
#define ACC_TERM(ES, SI) { \
        uint2 u = P[(SI) * FO4 + c]; \
        float2 f0 = __half22float2(*reinterpret_cast<__half2*>(&u.x)); \
        float2 f1 = __half22float2(*reinterpret_cast<__half2*>(&u.y)); \
        m.x += (ES) * f0.x; m.y += (ES) * f0.y; \
        m.z += (ES) * f1.x; m.w += (ES) * f1.y; }
        ACC_TERM(ea.x, 0) ACC_TERM(ea.y, 1) ACC_TERM(ea.z, 2) ACC_TERM(ea.w, 3)
        ACC_TERM(eb.x, 4) ACC_TERM(eb.y, 5) ACC_TERM(eb.z, 6) ACC_TERM(eb.w, 7)
#undef ACC_TERM
        asm volatile("red.global.add.v4.f32 [%0], {%1,%2,%3,%4};"
                     :: "l"(dst + c * 4), "f"(m.x), "f"(m.y), "f"(m.z), "f"(m.w)
                     : "memory");
    }
}

// ---------------- mega kernel: pool + whole MLP (64 x 512) ----------------
// Also zeroes g_deg for the next call (its only consumer is next call's hist).
__global__ __launch_bounds__(512) void k_mega(
    const float* __restrict__ Wd1, const float* __restrict__ bd1,
    const float* __restrict__ Wd2, const float* __restrict__ bd2,
    const float* __restrict__ Wd3, const float* __restrict__ bd3,
    const float* __restrict__ Wd4, const float* __restrict__ bd4,
    const float* __restrict__ Wd5, const float* __restrict__ bd5,
    const float* __restrict__ Wd6, const float* __restrict__ bd6,
    float* __restrict__ out)
{
    __shared__ float w3s[256 * 12];
    __shared__ float w4s[768 * 8];
    __shared__ float w5s[512];
    __shared__ float a2[256];
    __shared__ float a3[768];
    __shared__ float v0[24];
    __shared__ float a1[96];
    __shared__ float poolacc[21][24];
    __shared__ float bd3s[12], bd4s[8];
    __shared__ float red8[8];

    int t = threadIdx.x;
    int b = blockIdx.x;
    int epoch = 0;

    // zero g_deg for next call's hist
    for (int i = b * 512 + t; i < N_NODES; i += MEGA_NB * 512) g_deg[i] = 0;

    for (int idx = t; idx < 256 * 12; idx += 512) {
        int i = idx / 12, j = idx % 12;
        w3s[idx] = Wd3[i * 768 + b * 12 + j];
    }
    for (int idx = t; idx < 768 * 8; idx += 512) {
        int i = idx / 8, j = idx % 8;
        w4s[idx] = Wd4[i * 512 + b * 8 + j];
    }
    if (t < 512) w5s[t] = Wd5[t * 64 + b];
    if (t < 12) bd3s[t] = bd3[b * 12 + t];
    if (t < 8)  bd4s[t] = bd4[b * 8 + t];
    float bd5b = bd5[b];
    float wd6b = Wd6[b];

    // phase P: pool partials (21 row-slots per block)
    {
        int c = t % 24, slot = t / 24;
        if (slot < 21) {
            float local = 0.0f;
            for (int r = b * 21 + slot; r < N_NODES; r += MEGA_NB * 21)
                local += fmaxf(__ldcg(&g_AGG3[r * 24 + c]), 0.0f);
            poolacc[slot][c] = local;
        }
        __syncthreads();
        if (t < 24) {
            float s = 0.0f;
#pragma unroll
            for (int k = 0; k < 21; k++) s += poolacc[k][t];
            g_poolpart[b * 24 + t] = s;
        }
    }
    gridbar(&g_barcnt, epoch, MEGA_NB);   // 1

    // phase A: block 0 does L1 (24->96) + L2 (96->256)
    if (b == 0) {
        if (t < 24) {
            float s = 0.0f;
            for (int k = 0; k < MEGA_NB; k++) s += __ldcg(&g_poolpart[k * 24 + t]);
            v0[t] = s;
        }
        __syncthreads();
        if (t < 96) {
            float acc = bd1[t];
#pragma unroll
            for (int i = 0; i < 24; i++) acc += v0[i] * Wd1[i * 96 + t];
            a1[t] = fmaxf(acc, 0.0f);
        }
        __syncthreads();
        if (t < 256) {
            float acc = bd2[t];
#pragma unroll 8
            for (int i = 0; i < 96; i++) acc += a1[i] * Wd2[i * 256 + t];
            g_v1[t] = fmaxf(acc, 0.0f);
        }
    }
    gridbar(&g_barcnt, epoch, MEGA_NB);   // 2

    // phase B: L3 256->768, 12 outputs per block (16 threads each)
    if (t < 256) a2[t] = __ldcg(&g_v1[t]);
    __syncthreads();
    if (t < 192) {
        int jj = t >> 4, kk = t & 15;
        float acc = 0.0f;
#pragma unroll
        for (int r = 0; r < 16; r++) {
            int i = kk + 16 * r;
            acc += a2[i] * w3s[i * 12 + jj];
        }
#pragma unroll
        for (int off = 8; off >= 1; off >>= 1)
            acc += __shfl_down_sync(0xffffffffu, acc, off, 16);
        if (kk == 0) g_v2[b * 12 + jj] = fmaxf(acc + bd3s[jj], 0.0f);
    }
    gridbar(&g_barcnt, epoch, MEGA_NB);   // 3

    // phase C: L4 768->512, 8 outputs per block
    if (t < 256) {
#pragma unroll
        for (int k = 0; k < 3; k++) a3[t + k * 256] = __ldcg(&g_v2[t + k * 256]);
    }
    __syncthreads();
    if (t < 256) {
        int w = t >> 5, l = t & 31;
        float acc = 0.0f;
#pragma unroll
        for (int k = 0; k < 24; k++) {
            int i = l + 32 * k;
            acc += a3[i] * w4s[i * 8 + w];
        }
#pragma unroll
        for (int off = 16; off >= 1; off >>= 1)
            acc += __shfl_down_sync(0xffffffffu, acc, off);
        if (l == 0) g_v3[b * 8 + w] = fmaxf(acc + bd4s[w], 0.0f);
    }
    gridbar(&g_barcnt, epoch, MEGA_NB);   // 4

    // phase D: L5 512->64 (output b) * W6[b]
    if (t < 256) {
        float acc = __ldcg(&g_v3[t]) * w5s[t] + __ldcg(&g_v3[t + 256]) * w5s[t + 256];
#pragma unroll
        for (int off = 16; off >= 1; off >>= 1)
            acc += __shfl_down_sync(0xffffffffu, acc, off);
        int w = t >> 5, l = t & 31;
        if (l == 0) red8[w] = acc;
    }
    __syncthreads();
    if (t == 0) {
        float s = 0.0f;
#pragma unroll
        for (int k = 0; k < 8; k++) s += red8[k];
        g_v3r[b] = fmaxf(s + bd5b, 0.0f) * wd6b;
    }
    gridbar(&g_barcnt, epoch, MEGA_NB);   // 5

    // phase E: block 0 final
    if (b == 0 && t == 0) {
        float s = bd6[0];
#pragma unroll
        for (int k = 0; k < 64; k++) s += __ldcg(&g_v3r[k]);
        out[0] = s;
    }
}

// ---------------- launcher ----------------
extern "C" void kernel_launch(void* const* d_in, const int* in_sizes, int n_in,
                              void* d_out, int out_size)
{
    const float* x    = (const float*)d_in[0];
    const int*   ei   = (const int*)d_in[1];
    const float* e    = (const float*)d_in[2];
    const float* We1  = (const float*)d_in[3];
    const float* be1  = (const float*)d_in[4];
    const float* root1= (const float*)d_in[5];
    const float* b1   = (const float*)d_in[6];
    const float* We2  = (const float*)d_in[7];
    const float* be2  = (const float*)d_in[8];
    const float* root2= (const float*)d_in[9];
    const float* b2   = (const float*)d_in[10];
    const float* We3  = (const float*)d_in[11];
    const float* be3  = (const float*)d_in[12];
    const float* root3= (const float*)d_in[13];
    const float* b3   = (const float*)d_in[14];
    const float* Wd1  = (const float*)d_in[15];
    const float* bd1  = (const float*)d_in[16];
    const float* Wd2  = (const float*)d_in[17];
    const float* bd2  = (const float*)d_in[18];
    const float* Wd3  = (const float*)d_in[19];
    const float* bd3  = (const float*)d_in[20];
    const float* Wd4  = (const float*)d_in[21];
    const float* bd4  = (const float*)d_in[22];
    const float* Wd5  = (const float*)d_in[23];
    const float* bd5  = (const float*)d_in[24];
    const float* Wd6  = (const float*)d_in[25];
    const float* bd6  = (const float*)d_in[26];

    const int2* ei2 = (const int2*)ei;
    const float4* e4 = (const float4*)e;

    const int ntile = (N_NODES + 255) / 256;                 // 79
    const int flat_grid = (N_EDGES + 255) / 256;             // 625
    const int edge_grid40 = (5 * N_EDGES + 255) / 256;       // 3125
    const int edge_grid24 = (3 * N_EDGES + 255) / 256;       // 1875

    k1_node1_hist<<<395 + 625, 256>>>(x, We1, be1, root1, b1, ei2);
    k_scanAB<<<40, 512>>>();
    k_scatter<<<flat_grid, 256>>>(ei2, e4);
    k_edge<1, 40, 5><<<edge_grid40, 256>>>();
    k_node<2, 40, 24, 5><<<dim3(ntile, 3), 256>>>(We2, be2, root2, b2);
    k_edge<2, 24, 3><<<edge_grid24, 256>>>();
    k_node<3, 24, 24, 5><<<dim3(ntile, 3), 256>>>(We3, be3, root3, b3);
    k_edge<3, 24, 3><<<edge_grid24, 256>>>();
    k_mega<<<MEGA_NB, 512>>>(Wd1, bd1, Wd2, bd2, Wd3, bd3, Wd4, bd4, Wd5, bd5,
                             Wd6, bd6, (float*)d_out);
}

// round 12
// speedup vs baseline: 1.8474x; 1.1310x over previous
#include <cuda_runtime.h>
#include <cuda_fp16.h>

// ---------------- problem constants ----------------
#define N_NODES 20000
#define N_EDGES 160000
#define MEGA_NB 64

// ---------------- device scratch (static; no allocs) ----------------
// P̄[n, s, o]: s=0..7 edge-weight slots, s=8 = R (unit coefficient). fp16.
__device__ __align__(16) __half g_Ph[N_NODES * 360];  // max 9*40 cols
__device__ __align__(16) float g_AGG1[N_NODES * 40];
__device__ __align__(16) float g_AGG2[N_NODES * 24];
__device__ __align__(16) float g_AGG3[N_NODES * 24];
__device__ int   g_deg[N_NODES];    // zero at load; re-zeroed by k_mega each call
__device__ int   g_cursor[N_NODES];
__device__ int   g_bsum[40];
__device__ __align__(8)  int2   g_srt[N_EDGES];        // (src, tgt) sorted by src
__device__ __align__(16) float4 g_eperm[N_EDGES * 2];  // e payload, src-sorted
__device__ float g_poolpart[MEGA_NB * 24];
__device__ __align__(16) float g_v2[768];
__device__ __align__(16) float g_v3[512];
__device__ float g_v3r[64];
__device__ unsigned g_barS;    // scanAB barrier
__device__ unsigned g_barcnt;  // mega barrier

// ---------------- helpers ----------------
__device__ __forceinline__ void ffma2(unsigned long long& d, unsigned long long a,
                                      unsigned long long b) {
    asm("fma.rn.f32x2 %0, %1, %2, %0;" : "+l"(d) : "l"(a), "l"(b));
}
__device__ __forceinline__ unsigned long long packf2(float x) {
    unsigned long long r;
    asm("mov.b64 %0, {%1, %1};" : "=l"(r) : "f"(x));
    return r;
}
__device__ __forceinline__ float2 unpackf2(unsigned long long v) {
    float2 f;
    asm("mov.b64 {%0, %1}, %2;" : "=f"(f.x), "=f"(f.y) : "l"(v));
    return f;
}
__device__ __forceinline__ void gridbar(unsigned* cnt, int& epoch, int nb) {
    __threadfence();
    __syncthreads();
    epoch++;
    if (threadIdx.x == 0) {
        atomicAdd(cnt, 1u);
        unsigned target = (unsigned)epoch * (unsigned)nb;
        while (*((volatile unsigned*)cnt) < target) __nanosleep(20);
    }
    __syncthreads();
}

// ---------------- k1: node1 (blocks 0..394) || hist (blocks 395..1019) ----------------
// node1: cols [0,360) P̄(fp16, incl. R at s=8), [360,400) AGG1(+bias).
__global__ __launch_bounds__(256) void k1_node1_hist(
    const float* __restrict__ xin,
    const float* __restrict__ We, const float* __restrict__ be,
    const float* __restrict__ root, const float* __restrict__ bias,
    const int2* __restrict__ ei)
{
    constexpr int FI = 16, FO = 40, CC = 5;
    constexpr int CC16 = CC * 16;
    __shared__ __align__(16) float Wsh[FI * CC16];
    __shared__ float bsh[FO];
    int t = threadIdx.x;
    int b = blockIdx.x;

    if (b >= 395) {   // histogram blocks (full 160k-thread parallelism)
        int i = (b - 395) * 256 + t;
        if (i < N_EDGES) atomicAdd(&g_deg[ei[i].x], 1);
        return;
    }

    int bx = b % 79;        // node tile
    int by = b / 79;        // col chunk
    int cg0 = by * CC;
    int colbase = cg0 * 16;

    if (b == 0 && t == 0) { g_barS = 0u; g_barcnt = 0u; }

    for (int idx = t; idx < FI * CC16; idx += 256) {
        int f = idx / CC16, cl = idx % CC16;
        int c = colbase + cl;
        float w;
        if (c < 8 * FO) {
            int s = c / FO, o = c % FO;
            w = We[s * (FI * FO) + f * FO + o];
        } else if (c < 9 * FO) {
            int o = c - 8 * FO;
            w = be[f * FO + o];
        } else {
            int o = c - 9 * FO;
            w = root[f * FO + o];
        }
        Wsh[idx] = w;
    }
    for (int idx = t; idx < FO; idx += 256) bsh[idx] = bias[idx];
    __syncthreads();

    int node = bx * 256 + t;
    if (node >= N_NODES) return;

    float h[FI];
    const float4* hv = reinterpret_cast<const float4*>(xin + (size_t)node * FI);
#pragma unroll
    for (int f4 = 0; f4 < FI / 4; f4++) {
        float4 a = hv[f4];
        h[4*f4+0]=a.x; h[4*f4+1]=a.y; h[4*f4+2]=a.z; h[4*f4+3]=a.w;
    }

    const ulonglong2* Wv = reinterpret_cast<const ulonglong2*>(Wsh);
    uint2* Pv = reinterpret_cast<uint2*>(g_Ph) + (size_t)node * (9 * FO / 4);
    float4* Av = reinterpret_cast<float4*>(g_AGG1) + (size_t)node * (FO / 4);

#pragma unroll
    for (int cg = 0; cg < CC; cg++) {
        unsigned long long acc[8];
#pragma unroll
        for (int k = 0; k < 8; k++) acc[k] = 0ull;
#pragma unroll
        for (int f = 0; f < FI; f++) {
            const ulonglong2* wrow = Wv + f * (CC * 4) + cg * 4;
            ulonglong2 wA = wrow[0], wB = wrow[1], wC = wrow[2], wD = wrow[3];
            unsigned long long ha = packf2(h[f]);
            ffma2(acc[0], ha, wA.x); ffma2(acc[1], ha, wA.y);
            ffma2(acc[2], ha, wB.x); ffma2(acc[3], ha, wB.y);
            ffma2(acc[4], ha, wC.x); ffma2(acc[5], ha, wC.y);
            ffma2(acc[6], ha, wD.x); ffma2(acc[7], ha, wD.y);
        }
#pragma unroll
        for (int q = 0; q < 4; q++) {
            int cb = (cg0 + cg) * 16 + q * 4;
            float2 a0 = unpackf2(acc[2*q]), a1 = unpackf2(acc[2*q+1]);
            float4 va = make_float4(a0.x, a0.y, a1.x, a1.y);
            if (cb < 9 * FO) {
                union { __half2 h2[2]; uint2 u; } pk;
                pk.h2[0] = __floats2half2_rn(va.x, va.y);
                pk.h2[1] = __floats2half2_rn(va.z, va.w);
                Pv[cb / 4] = pk.u;
            } else {
                int o = cb - 9 * FO;
                va.x += bsh[o]; va.y += bsh[o+1]; va.z += bsh[o+2]; va.w += bsh[o+3];
                Av[o / 4] = va;
            }
        }
    }
}

// ---------------- k2: fused two-level scan (40 blocks x 512, 1 gridbar) ----------------
__global__ __launch_bounds__(512) void k_scanAB()
{
    __shared__ int wred[16];
    __shared__ int bs[40];
    __shared__ int base;
    __shared__ int wsum[16];
    int t = threadIdx.x;
    int lane = t & 31, w = t >> 5;
    int b = blockIdx.x;
    int epoch = 0;

    int idx = b * 500 + t;
    int d = (t < 500 && idx < N_NODES) ? g_deg[idx] : 0;

    {
        int s = d;
#pragma unroll
        for (int off = 16; off >= 1; off >>= 1)
            s += __shfl_down_sync(0xffffffffu, s, off);
        if (lane == 0) wred[w] = s;
        __syncthreads();
        if (w == 0) {
            int v = (lane < 16) ? wred[lane] : 0;
#pragma unroll
            for (int off = 8; off >= 1; off >>= 1)
                v += __shfl_down_sync(0xffffffffu, v, off);
            if (lane == 0) g_bsum[b] = v;
        }
    }
    gridbar(&g_barS, epoch, 40);

    if (t < 40) bs[t] = g_bsum[t];
    __syncthreads();
    if (t == 0) {
        int s = 0;
#pragma unroll
        for (int i = 0; i < 40; i++) if (i < b) s += bs[i];
        base = s;
    }
    int sc = d;
#pragma unroll
    for (int off = 1; off < 32; off <<= 1) {
        int n = __shfl_up_sync(0xffffffffu, sc, off);
        if (lane >= off) sc += n;
    }
    if (lane == 31) wsum[w] = sc;
    __syncthreads();
    if (w == 0) {
        int v = (lane < 16) ? wsum[lane] : 0;
#pragma unroll
        for (int off = 1; off < 16; off <<= 1) {
            int n = __shfl_up_sync(0xffffffffu, v, off);
            if (lane >= off) v += n;
        }
        if (lane < 16) wsum[lane] = v;
    }
    __syncthreads();
    int wbase = (w == 0) ? 0 : wsum[w - 1];
    if (t < 500 && idx < N_NODES) g_cursor[idx] = base + wbase + sc - d;
}

// ---------------- k3: scatter (1 edge/thread) ----------------
__global__ void k_scatter(const int2* __restrict__ ei, const float4* __restrict__ e4) {
    int i = blockIdx.x * blockDim.x + threadIdx.x;
    if (i < N_EDGES) {
        int2 st = ei[i];
        float4 a = e4[2 * i], b = e4[2 * i + 1];
        int p = atomicAdd(&g_cursor[st.x], 1);
        g_srt[p] = st;
        g_eperm[2 * p] = a;
        g_eperm[2 * p + 1] = b;
    }
}

// ---------------- node kernel (layers 2/3) ----------------
template <int LAYER, int FI, int FO, int CC>
__global__ __launch_bounds__(256) void k_node(
    const float* __restrict__ We, const float* __restrict__ be,
    const float* __restrict__ root, const float* __restrict__ bias)
{
    constexpr int CC16 = CC * 16;
    __shared__ __align__(16) float Wsh[FI * CC16];
    __shared__ float bsh[FO];
    int t = threadIdx.x;
    int cg0 = blockIdx.y * CC;
    int colbase = cg0 * 16;

    for (int idx = t; idx < FI * CC16; idx += 256) {
        int f = idx / CC16, cl = idx % CC16;
        int c = colbase + cl;
        float w;
        if (c < 8 * FO) {
            int s = c / FO, o = c % FO;
            w = We[s * (FI * FO) + f * FO + o];
        } else if (c < 9 * FO) {
            int o = c - 8 * FO;
            w = be[f * FO + o];
        } else {
            int o = c - 9 * FO;
            w = root[f * FO + o];
        }
        Wsh[idx] = w;
    }
    for (int idx = t; idx < FO; idx += 256) bsh[idx] = bias[idx];
    __syncthreads();

    int node = blockIdx.x * 256 + t;
    if (node >= N_NODES) return;

    const float* hin = (LAYER == 2) ? g_AGG1 : g_AGG2;
    float* AGG       = (LAYER == 2) ? g_AGG2 : g_AGG3;

    float h[FI];
    const float4* hv = reinterpret_cast<const float4*>(hin + (size_t)node * FI);
#pragma unroll
    for (int f4 = 0; f4 < FI / 4; f4++) {
        float4 a = hv[f4];
        a.x = fmaxf(a.x, 0.f); a.y = fmaxf(a.y, 0.f);
        a.z = fmaxf(a.z, 0.f); a.w = fmaxf(a.w, 0.f);
        h[4*f4+0]=a.x; h[4*f4+1]=a.y; h[4*f4+2]=a.z; h[4*f4+3]=a.w;
    }

    const ulonglong2* Wv = reinterpret_cast<const ulonglong2*>(Wsh);
    uint2* Pv = reinterpret_cast<uint2*>(g_Ph) + (size_t)node * (9 * FO / 4);
    float4* Av = reinterpret_cast<float4*>(AGG) + (size_t)node * (FO / 4);

#pragma unroll
    for (int cg = 0; cg < CC; cg++) {
        unsigned long long acc[8];
#pragma unroll
        for (int k = 0; k < 8; k++) acc[k] = 0ull;
#pragma unroll
        for (int f = 0; f < FI; f++) {
            const ulonglong2* wrow = Wv + f * (CC * 4) + cg * 4;
            ulonglong2 wA = wrow[0], wB = wrow[1], wC = wrow[2], wD = wrow[3];
            unsigned long long ha = packf2(h[f]);
            ffma2(acc[0], ha, wA.x); ffma2(acc[1], ha, wA.y);
            ffma2(acc[2], ha, wB.x); ffma2(acc[3], ha, wB.y);
            ffma2(acc[4], ha, wC.x); ffma2(acc[5], ha, wC.y);
            ffma2(acc[6], ha, wD.x); ffma2(acc[7], ha, wD.y);
        }
#pragma unroll
        for (int q = 0; q < 4; q++) {
            int cb = (cg0 + cg) * 16 + q * 4;
            float2 a0 = unpackf2(acc[2*q]), a1 = unpackf2(acc[2*q+1]);
            float4 va = make_float4(a0.x, a0.y, a1.x, a1.y);
            if (cb < 9 * FO) {
                union { __half2 h2[2]; uint2 u; } pk;
                pk.h2[0] = __floats2half2_rn(va.x, va.y);
                pk.h2[1] = __floats2half2_rn(va.z, va.w);
                Pv[cb / 4] = pk.u;
            } else {
                int o = cb - 9 * FO;
                va.x += bsh[o]; va.y += bsh[o+1]; va.z += bsh[o+2]; va.w += bsh[o+3];
                Av[o / 4] = va;
            }
        }
    }
}

// ---------------- edge kernel ----------------
// TPE threads per edge, FO4/TPE chunks each. msg = P̄[8] + Σ_s e_s·P̄[s], all fp16 loads.
template <int LAYER, int FO, int TPE>
__global__ __launch_bounds__(256) void k_edge()
{
    constexpr int FO4 = FO / 4;
    constexpr int CH = FO4 / TPE;
    int gid = blockIdx.x * 256 + threadIdx.x;
    int edge = gid / TPE;
    if (edge >= N_EDGES) return;
    int part = gid - edge * TPE;

    int2 st = g_srt[edge];
    float4 ea = g_eperm[2 * edge];
    float4 eb = g_eperm[2 * edge + 1];

    const uint2* P = reinterpret_cast<const uint2*>(g_Ph)
                     + (size_t)st.x * (9 * FO4) + part * CH;
    float* AGG;
    if (LAYER == 1)      AGG = g_AGG1;
    else if (LAYER == 2) AGG = g_AGG2;
    else                 AGG = g_AGG3;
    float* dst = AGG + (size_t)st.y * FO + part * CH * 4;

#pragma unroll
    for (int c = 0; c < CH; c++) {
        float4 m;
        {   // R term (s=8, unit coefficient)
            uint2 u = P[8 * FO4 + c];
            float2 f0 = __half22float2(*reinterpret_cast<__half2*>(&u.x));
            float2 f1 = __half22float2(*reinterpret_cast<__half2*>(&u.y));
            m = make_float4(f0.x, f0.y, f1.x, f1.y);
        }
#define ACC_TERM(ES, SI) { \
        uint2 u = P[(SI) * FO4 + c]; \
        float2 f0 = __half22float2(*reinterpret_cast<__half2*>(&u.x)); \
        float2 f1 = __half22float2(*reinterpret_cast<__half2*>(&u.y)); \
        m.x += (ES) * f0.x; m.y += (ES) * f0.y; \
        m.z += (ES) * f1.x; m.w += (ES) * f1.y; }
        ACC_TERM(ea.x, 0) ACC_TERM(ea.y, 1) ACC_TERM(ea.z, 2) ACC_TERM(ea.w, 3)
        ACC_TERM(eb.x, 4) ACC_TERM(eb.y, 5) ACC_TERM(eb.z, 6) ACC_TERM(eb.w, 7)
#undef ACC_TERM
        asm volatile("red.global.add.v4.f32 [%0], {%1,%2,%3,%4};"
                     :: "l"(dst + c * 4), "f"(m.x), "f"(m.y), "f"(m.z), "f"(m.w)
                     : "memory");
    }
}

// ---------------- mega kernel: pool + whole MLP (64 x 512, 4 gridbars) ----------------
// L1/L2 computed redundantly per block (no block-0 serialization, one fewer bar).
// Also zeroes g_deg for the next call.
__global__ __launch_bounds__(512) void k_mega(
    const float* __restrict__ Wd1, const float* __restrict__ bd1,
    const float* __restrict__ Wd2, const float* __restrict__ bd2,
    const float* __restrict__ Wd3, const float* __restrict__ bd3,
    const float* __restrict__ Wd4, const float* __restrict__ bd4,
    const float* __restrict__ Wd5, const float* __restrict__ bd5,
    const float* __restrict__ Wd6, const float* __restrict__ bd6,
    float* __restrict__ out)
{
    __shared__ float w3s[256 * 12];
    __shared__ float w4s[768 * 8];
    __shared__ float w5s[512];
    __shared__ float a2[256];
    __shared__ float a3[768];
    __shared__ float v0[24];
    __shared__ float a1[96];
    __shared__ float poolacc[21][24];
    __shared__ float bd3s[12], bd4s[8];
    __shared__ float red8[8];

    int t = threadIdx.x;
    int b = blockIdx.x;
    int epoch = 0;

    // zero g_deg for next call's hist
    for (int i = b * 512 + t; i < N_NODES; i += MEGA_NB * 512) g_deg[i] = 0;

    for (int idx = t; idx < 256 * 12; idx += 512) {
        int i = idx / 12, j = idx % 12;
        w3s[idx] = Wd3[i * 768 + b * 12 + j];
    }
    for (int idx = t; idx < 768 * 8; idx += 512) {
        int i = idx / 8, j = idx % 8;
        w4s[idx] = Wd4[i * 512 + b * 8 + j];
    }
    if (t < 512) w5s[t] = Wd5[t * 64 + b];
    if (t < 12) bd3s[t] = bd3[b * 12 + t];
    if (t < 8)  bd4s[t] = bd4[b * 8 + t];
    float bd5b = bd5[b];
    float wd6b = Wd6[b];

    // phase P: pool partials (21 row-slots per block)
    {
        int c = t % 24, slot = t / 24;
        if (slot < 21) {
            float local = 0.0f;
            for (int r = b * 21 + slot; r < N_NODES; r += MEGA_NB * 21)
                local += fmaxf(__ldcg(&g_AGG3[r * 24 + c]), 0.0f);
            poolacc[slot][c] = local;
        }
        __syncthreads();
        if (t < 24) {
            float s = 0.0f;
#pragma unroll
            for (int k = 0; k < 21; k++) s += poolacc[k][t];
            g_poolpart[b * 24 + t] = s;
        }
    }
    gridbar(&g_barcnt, epoch, MEGA_NB);   // 1

    // phase A (redundant per block): pool reduce + L1 (24->96) + L2 (96->256)
    if (t < 24) {
        float s = 0.0f;
        for (int k = 0; k < MEGA_NB; k++) s += __ldcg(&g_poolpart[k * 24 + t]);
        v0[t] = s;
    }
    __syncthreads();
    if (t < 96) {
        float acc = bd1[t];
#pragma unroll
        for (int i = 0; i < 24; i++) acc += v0[i] * Wd1[i * 96 + t];
        a1[t] = fmaxf(acc, 0.0f);
    }
    __syncthreads();
    if (t < 256) {
        float acc = bd2[t];
#pragma unroll 8
        for (int i = 0; i < 96; i++) acc += a1[i] * Wd2[i * 256 + t];
        a2[t] = fmaxf(acc, 0.0f);
    }
    __syncthreads();

    // phase B: L3 256->768, 12 outputs per block (16 threads each)
    if (t < 192) {
        int jj = t >> 4, kk = t & 15;
        float acc = 0.0f;
#pragma unroll
        for (int r = 0; r < 16; r++) {
            int i = kk + 16 * r;
            acc += a2[i] * w3s[i * 12 + jj];
        }
#pragma unroll
        for (int off = 8; off >= 1; off >>= 1)
            acc += __shfl_down_sync(0xffffffffu, acc, off, 16);
        if (kk == 0) g_v2[b * 12 + jj] = fmaxf(acc + bd3s[jj], 0.0f);
    }
    gridbar(&g_barcnt, epoch, MEGA_NB);   // 2

    // phase C: L4 768->512, 8 outputs per block
    if (t < 256) {
#pragma unroll
        for (int k = 0; k < 3; k++) a3[t + k * 256] = __ldcg(&g_v2[t + k * 256]);
    }
    __syncthreads();
    if (t < 256) {
        int w = t >> 5, l = t & 31;
        float acc = 0.0f;
#pragma unroll
        for (int k = 0; k < 24; k++) {
            int i = l + 32 * k;
            acc += a3[i] * w4s[i * 8 + w];
        }
#pragma unroll
        for (int off = 16; off >= 1; off >>= 1)
            acc += __shfl_down_sync(0xffffffffu, acc, off);
        if (l == 0) g_v3[b * 8 + w] = fmaxf(acc + bd4s[w], 0.0f);
    }
    gridbar(&g_barcnt, epoch, MEGA_NB);   // 3

    // phase D: L5 512->64 (output b) * W6[b]
    if (t < 256) {
        float acc = __ldcg(&g_v3[t]) * w5s[t] + __ldcg(&g_v3[t + 256]) * w5s[t + 256];
#pragma unroll
        for (int off = 16; off >= 1; off >>= 1)
            acc += __shfl_down_sync(0xffffffffu, acc, off);
        int w = t >> 5, l = t & 31;
        if (l == 0) red8[w] = acc;
    }
    __syncthreads();
    if (t == 0) {
        float s = 0.0f;
#pragma unroll
        for (int k = 0; k < 8; k++) s += red8[k];
        g_v3r[b] = fmaxf(s + bd5b, 0.0f) * wd6b;
    }
    gridbar(&g_barcnt, epoch, MEGA_NB);   // 4

    // phase E: block 0 final
    if (b == 0 && t == 0) {
        float s = bd6[0];
#pragma unroll
        for (int k = 0; k < 64; k++) s += __ldcg(&g_v3r[k]);
        out[0] = s;
    }
}

// ---------------- launcher ----------------
extern "C" void kernel_launch(void* const* d_in, const int* in_sizes, int n_in,
                              void* d_out, int out_size)
{
    const float* x    = (const float*)d_in[0];
    const int*   ei   = (const int*)d_in[1];
    const float* e    = (const float*)d_in[2];
    const float* We1  = (const float*)d_in[3];
    const float* be1  = (const float*)d_in[4];
    const float* root1= (const float*)d_in[5];
    const float* b1   = (const float*)d_in[6];
    const float* We2  = (const float*)d_in[7];
    const float* be2  = (const float*)d_in[8];
    const float* root2= (const float*)d_in[9];
    const float* b2   = (const float*)d_in[10];
    const float* We3  = (const float*)d_in[11];
    const float* be3  = (const float*)d_in[12];
    const float* root3= (const float*)d_in[13];
    const float* b3   = (const float*)d_in[14];
    const float* Wd1  = (const float*)d_in[15];
    const float* bd1  = (const float*)d_in[16];
    const float* Wd2  = (const float*)d_in[17];
    const float* bd2  = (const float*)d_in[18];
    const float* Wd3  = (const float*)d_in[19];
    const float* bd3  = (const float*)d_in[20];
    const float* Wd4  = (const float*)d_in[21];
    const float* bd4  = (const float*)d_in[22];
    const float* Wd5  = (const float*)d_in[23];
    const float* bd5  = (const float*)d_in[24];
    const float* Wd6  = (const float*)d_in[25];
    const float* bd6  = (const float*)d_in[26];

    const int2* ei2 = (const int2*)ei;
    const float4* e4 = (const float4*)e;

    const int ntile = (N_NODES + 255) / 256;                 // 79
    const int flat_grid = (N_EDGES + 255) / 256;             // 625
    const int edge_grid40 = (5 * N_EDGES + 255) / 256;       // 3125
    const int edge_grid24 = (3 * N_EDGES + 255) / 256;       // 1875

    k1_node1_hist<<<395 + 625, 256>>>(x, We1, be1, root1, b1, ei2);
    k_scanAB<<<40, 512>>>();
    k_scatter<<<flat_grid, 256>>>(ei2, e4);
    k_edge<1, 40, 5><<<edge_grid40, 256>>>();
    k_node<2, 40, 24, 5><<<dim3(ntile, 3), 256>>>(We2, be2, root2, b2);
    k_edge<2, 24, 3><<<edge_grid24, 256>>>();
    k_node<3, 24, 24, 5><<<dim3(ntile, 3), 256>>>(We3, be3, root3, b3);
    k_edge<3, 24, 3><<<edge_grid24, 256>>>();
    k_mega<<<MEGA_NB, 512>>>(Wd1, bd1, Wd2, bd2, Wd3, bd3, Wd4, bd4, Wd5, bd5,
                             Wd6, bd6, (float*)d_out);
}

// round 13
// speedup vs baseline: 1.8826x; 1.0191x over previous
#include <cuda_runtime.h>
#include <cuda_fp16.h>

// ---------------- problem constants ----------------
#define N_NODES 20000
#define N_EDGES 160000
#define MEGA_NB 64

// ---------------- device scratch (static; no allocs) ----------------
// P̄[n, s, o]: s=0..7 edge-weight slots, s=8 = R (unit coefficient). fp16.
__device__ __align__(16) __half g_Ph[N_NODES * 360];  // max 9*40 cols
__device__ __align__(16) float g_AGG1[N_NODES * 40];
__device__ __align__(16) float g_AGG2[N_NODES * 24];
__device__ __align__(16) float g_AGG3[N_NODES * 24];
__device__ int   g_deg[N_NODES];    // zero at load; re-zeroed by k_mega each call
__device__ int   g_cursor[N_NODES];
__device__ int   g_bsum[40];
__device__ __align__(8)  int2   g_srt[N_EDGES];       // (src, tgt) sorted by src
__device__ __align__(16) __half g_eperm_h[N_EDGES * 8];  // e payload fp16, src-sorted
__device__ float g_poolpart[MEGA_NB * 24];
__device__ __align__(16) float g_v2[768];
__device__ __align__(16) float g_v3[512];
__device__ float g_v3r[64];
__device__ unsigned g_barS;    // scanAB barrier
__device__ unsigned g_barcnt;  // mega barrier
__device__ unsigned g_done;    // mega last-block ticket

// ---------------- helpers ----------------
__device__ __forceinline__ void ffma2(unsigned long long& d, unsigned long long a,
                                      unsigned long long b) {
    asm("fma.rn.f32x2 %0, %1, %2, %0;" : "+l"(d) : "l"(a), "l"(b));
}
__device__ __forceinline__ unsigned long long packf2(float x) {
    unsigned long long r;
    asm("mov.b64 %0, {%1, %1};" : "=l"(r) : "f"(x));
    return r;
}
__device__ __forceinline__ float2 unpackf2(unsigned long long v) {
    float2 f;
    asm("mov.b64 {%0, %1}, %2;" : "=f"(f.x), "=f"(f.y) : "l"(v));
    return f;
}
__device__ __forceinline__ void gridbar(unsigned* cnt, int& epoch, int nb) {
    __threadfence();
    __syncthreads();
    epoch++;
    if (threadIdx.x == 0) {
        atomicAdd(cnt, 1u);
        unsigned target = (unsigned)epoch * (unsigned)nb;
        while (*((volatile unsigned*)cnt) < target) __nanosleep(20);
    }
    __syncthreads();
}

// ---------------- k1: node1 (blocks 0..394) || hist (blocks 395..1019) ----------------
// node1: cols [0,360) P̄(fp16, incl. R at s=8), [360,400) AGG1(+bias).
__global__ __launch_bounds__(256) void k1_node1_hist(
    const float* __restrict__ xin,
    const float* __restrict__ We, const float* __restrict__ be,
    const float* __restrict__ root, const float* __restrict__ bias,
    const int2* __restrict__ ei)
{
    constexpr int FI = 16, FO = 40, CC = 5;
    constexpr int CC16 = CC * 16;
    __shared__ __align__(16) float Wsh[FI * CC16];
    __shared__ float bsh[FO];
    int t = threadIdx.x;
    int b = blockIdx.x;

    if (b >= 395) {   // histogram blocks (full 160k-thread parallelism)
        int i = (b - 395) * 256 + t;
        if (i < N_EDGES) atomicAdd(&g_deg[ei[i].x], 1);
        return;
    }

    int bx = b % 79;        // node tile
    int by = b / 79;        // col chunk
    int cg0 = by * CC;
    int colbase = cg0 * 16;

    if (b == 0 && t == 0) { g_barS = 0u; g_barcnt = 0u; g_done = 0u; }

    for (int idx = t; idx < FI * CC16; idx += 256) {
        int f = idx / CC16, cl = idx % CC16;
        int c = colbase + cl;
        float w;
        if (c < 8 * FO) {
            int s = c / FO, o = c % FO;
            w = We[s * (FI * FO) + f * FO + o];
        } else if (c < 9 * FO) {
            int o = c - 8 * FO;
            w = be[f * FO + o];
        } else {
            int o = c - 9 * FO;
            w = root[f * FO + o];
        }
        Wsh[idx] = w;
    }
    for (int idx = t; idx < FO; idx += 256) bsh[idx] = bias[idx];
    __syncthreads();

    int node = bx * 256 + t;
    if (node >= N_NODES) return;

    float h[FI];
    const float4* hv = reinterpret_cast<const float4*>(xin + (size_t)node * FI);
#pragma unroll
    for (int f4 = 0; f4 < FI / 4; f4++) {
        float4 a = hv[f4];
        h[4*f4+0]=a.x; h[4*f4+1]=a.y; h[4*f4+2]=a.z; h[4*f4+3]=a.w;
    }

    const ulonglong2* Wv = reinterpret_cast<const ulonglong2*>(Wsh);
    uint2* Pv = reinterpret_cast<uint2*>(g_Ph) + (size_t)node * (9 * FO / 4);
    float4* Av = reinterpret_cast<float4*>(g_AGG1) + (size_t)node * (FO / 4);

#pragma unroll
    for (int cg = 0; cg < CC; cg++) {
        unsigned long long acc[8];
#pragma unroll
        for (int k = 0; k < 8; k++) acc[k] = 0ull;
#pragma unroll
        for (int f = 0; f < FI; f++) {
            const ulonglong2* wrow = Wv + f * (CC * 4) + cg * 4;
            ulonglong2 wA = wrow[0], wB = wrow[1], wC = wrow[2], wD = wrow[3];
            unsigned long long ha = packf2(h[f]);
            ffma2(acc[0], ha, wA.x); ffma2(acc[1], ha, wA.y);
            ffma2(acc[2], ha, wB.x); ffma2(acc[3], ha, wB.y);
            ffma2(acc[4], ha, wC.x); ffma2(acc[5], ha, wC.y);
            ffma2(acc[6], ha, wD.x); ffma2(acc[7], ha, wD.y);
        }
#pragma unroll
        for (int q = 0; q < 4; q++) {
            int cb = (cg0 + cg) * 16 + q * 4;
            float2 a0 = unpackf2(acc[2*q]), a1 = unpackf2(acc[2*q+1]);
            float4 va = make_float4(a0.x, a0.y, a1.x, a1.y);
            if (cb < 9 * FO) {
                union { __half2 h2[2]; uint2 u; } pk;
                pk.h2[0] = __floats2half2_rn(va.x, va.y);
                pk.h2[1] = __floats2half2_rn(va.z, va.w);
                Pv[cb / 4] = pk.u;
            } else {
                int o = cb - 9 * FO;
                va.x += bsh[o]; va.y += bsh[o+1]; va.z += bsh[o+2]; va.w += bsh[o+3];
                Av[o / 4] = va;
            }
        }
    }
}

// ---------------- k2: fused two-level scan (40 blocks x 512, 1 gridbar) ----------------
__global__ __launch_bounds__(512) void k_scanAB()
{
    __shared__ int wred[16];
    __shared__ int bs[40];
    __shared__ int base;
    __shared__ int wsum[16];
    int t = threadIdx.x;
    int lane = t & 31, w = t >> 5;
    int b = blockIdx.x;
    int epoch = 0;

    int idx = b * 500 + t;
    int d = (t < 500 && idx < N_NODES) ? g_deg[idx] : 0;

    {
        int s = d;
#pragma unroll
        for (int off = 16; off >= 1; off >>= 1)
            s += __shfl_down_sync(0xffffffffu, s, off);
        if (lane == 0) wred[w] = s;
        __syncthreads();
        if (w == 0) {
            int v = (lane < 16) ? wred[lane] : 0;
#pragma unroll
            for (int off = 8; off >= 1; off >>= 1)
                v += __shfl_down_sync(0xffffffffu, v, off);
            if (lane == 0) g_bsum[b] = v;
        }
    }
    gridbar(&g_barS, epoch, 40);

    if (t < 40) bs[t] = g_bsum[t];
    __syncthreads();
    if (t == 0) {
        int s = 0;
#pragma unroll
        for (int i = 0; i < 40; i++) if (i < b) s += bs[i];
        base = s;
    }
    int sc = d;
#pragma unroll
    for (int off = 1; off < 32; off <<= 1) {
        int n = __shfl_up_sync(0xffffffffu, sc, off);
        if (lane >= off) sc += n;
    }
    if (lane == 31) wsum[w] = sc;
    __syncthreads();
    if (w == 0) {
        int v = (lane < 16) ? wsum[lane] : 0;
#pragma unroll
        for (int off = 1; off < 16; off <<= 1) {
            int n = __shfl_up_sync(0xffffffffu, v, off);
            if (lane >= off) v += n;
        }
        if (lane < 16) wsum[lane] = v;
    }
    __syncthreads();
    int wbase = (w == 0) ? 0 : wsum[w - 1];
    if (t < 500 && idx < N_NODES) g_cursor[idx] = base + wbase + sc - d;
}

// ---------------- k3: scatter (1 edge/thread; e converted to fp16) ----------------
__global__ void k_scatter(const int2* __restrict__ ei, const float4* __restrict__ e4) {
    int i = blockIdx.x * blockDim.x + threadIdx.x;
    if (i < N_EDGES) {
        int2 st = ei[i];
        float4 a = e4[2 * i], b = e4[2 * i + 1];
        union { __half2 h2[4]; uint4 u; } pk;
        pk.h2[0] = __floats2half2_rn(a.x, a.y);
        pk.h2[1] = __floats2half2_rn(a.z, a.w);
        pk.h2[2] = __floats2half2_rn(b.x, b.y);
        pk.h2[3] = __floats2half2_rn(b.z, b.w);
        int p = atomicAdd(&g_cursor[st.x], 1);
        g_srt[p] = st;
        reinterpret_cast<uint4*>(g_eperm_h)[p] = pk.u;
    }
}

// ---------------- node kernel (layers 2/3) ----------------
template <int LAYER, int FI, int FO, int CC>
__global__ __launch_bounds__(256) void k_node(
    const float* __restrict__ We, const float* __restrict__ be,
    const float* __restrict__ root, const float* __restrict__ bias)
{
    constexpr int CC16 = CC * 16;
    __shared__ __align__(16) float Wsh[FI * CC16];
    __shared__ float bsh[FO];
    int t = threadIdx.x;
    int cg0 = blockIdx.y * CC;
    int colbase = cg0 * 16;

    for (int idx = t; idx < FI * CC16; idx += 256) {
        int f = idx / CC16, cl = idx % CC16;
        int c = colbase + cl;
        float w;
        if (c < 8 * FO) {
            int s = c / FO, o = c % FO;
            w = We[s * (FI * FO) + f * FO + o];
        } else if (c < 9 * FO) {
            int o = c - 8 * FO;
            w = be[f * FO + o];
        } else {
            int o = c - 9 * FO;
            w = root[f * FO + o];
        }
        Wsh[idx] = w;
    }
    for (int idx = t; idx < FO; idx += 256) bsh[idx] = bias[idx];
    __syncthreads();

    int node = blockIdx.x * 256 + t;
    if (node >= N_NODES) return;

    const float* hin = (LAYER == 2) ? g_AGG1 : g_AGG2;
    float* AGG       = (LAYER == 2) ? g_AGG2 : g_AGG3;

    float h[FI];
    const float4* hv = reinterpret_cast<const float4*>(hin + (size_t)node * FI);
#pragma unroll
    for (int f4 = 0; f4 < FI / 4; f4++) {
        float4 a = hv[f4];
        a.x = fmaxf(a.x, 0.f); a.y = fmaxf(a.y, 0.f);
        a.z = fmaxf(a.z, 0.f); a.w = fmaxf(a.w, 0.f);
        h[4*f4+0]=a.x; h[4*f4+1]=a.y; h[4*f4+2]=a.z; h[4*f4+3]=a.w;
    }

    const ulonglong2* Wv = reinterpret_cast<const ulonglong2*>(Wsh);
    uint2* Pv = reinterpret_cast<uint2*>(g_Ph) + (size_t)node * (9 * FO / 4);
    float4* Av = reinterpret_cast<float4*>(AGG) + (size_t)node * (FO / 4);

#pragma unroll
    for (int cg = 0; cg < CC; cg++) {
        unsigned long long acc[8];
#pragma unroll
        for (int k = 0; k < 8; k++) acc[k] = 0ull;
#pragma unroll
        for (int f = 0; f < FI; f++) {
            const ulonglong2* wrow = Wv + f * (CC * 4) + cg * 4;
            ulonglong2 wA = wrow[0], wB = wrow[1], wC = wrow[2], wD = wrow[3];
            unsigned long long ha = packf2(h[f]);
            ffma2(acc[0], ha, wA.x); ffma2(acc[1], ha, wA.y);
            ffma2(acc[2], ha, wB.x); ffma2(acc[3], ha, wB.y);
            ffma2(acc[4], ha, wC.x); ffma2(acc[5], ha, wC.y);
            ffma2(acc[6], ha, wD.x); ffma2(acc[7], ha, wD.y);
        }
#pragma unroll
        for (int q = 0; q < 4; q++) {
            int cb = (cg0 + cg) * 16 + q * 4;
            float2 a0 = unpackf2(acc[2*q]), a1 = unpackf2(acc[2*q+1]);
            float4 va = make_float4(a0.x, a0.y, a1.x, a1.y);
            if (cb < 9 * FO) {
                union { __half2 h2[2]; uint2 u; } pk;
                pk.h2[0] = __floats2half2_rn(va.x, va.y);
                pk.h2[1] = __floats2half2_rn(va.z, va.w);
                Pv[cb / 4] = pk.u;
            } else {
                int o = cb - 9 * FO;
                va.x += bsh[o]; va.y += bsh[o+1]; va.z += bsh[o+2]; va.w += bsh[o+3];
                Av[o / 4] = va;
            }
        }
    }
}

// ---------------- edge kernel ----------------
// TPE threads per edge, FO4/TPE chunks each. msg = P̄[8] + Σ_s e_s·P̄[s].
// P̄ and e both fp16; one uint4 e-load per thread.
template <int LAYER, int FO, int TPE>
__global__ __launch_bounds__(256) void k_edge()
{
    constexpr int FO4 = FO / 4;
    constexpr int CH = FO4 / TPE;
    int gid = blockIdx.x * 256 + threadIdx.x;
    int edge = gid / TPE;
    if (edge >= N_EDGES) return;
    int part = gid - edge * TPE;

    int2 st = g_srt[edge];
    uint4 eu = reinterpret_cast<const uint4*>(g_eperm_h)[edge];
    float2 e01 = __half22float2(*reinterpret_cast<__half2*>(&eu.x));
    float2 e23 = __half22float2(*reinterpret_cast<__half2*>(&eu.y));
    float2 e45 = __half22float2(*reinterpret_cast<__half2*>(&eu.z));
    float2 e67 = __half22float2(*reinterpret_cast<__half2*>(&eu.w));

    const uint2* P = reinterpret_cast<const uint2*>(g_Ph)
                     + (size_t)st.x * (9 * FO4) + part * CH;
    float* AGG;
    if (LAYER == 1)      AGG = g_AGG1;
    else if (LAYER == 2) AGG = g_AGG2;
    else                 AGG = g_AGG3;
    float* dst = AGG + (size_t)st.y * FO + part * CH * 4;

#pragma unroll
    for (int c = 0; c < CH; c++) {
        float4 m;
        {   // R term (s=8, unit coefficient)
            uint2 u = P[8 * FO4 + c];
            float2 f0 = __half22float2(*reinterpret_cast<__half2*>(&u.x));
            float2 f1 = __half22float2(*reinterpret_cast<__half2*>(&u.y));
            m = make_float4(f0.x, f0.y, f1.x, f1.y);
        }
#define ACC_TERM(ES, SI) { \
        uint2 u = P[(SI) * FO4 + c]; \
        float2 f0 = __half22float2(*reinterpret_cast<__half2*>(&u.x)); \
        float2 f1 = __half22float2(*reinterpret_cast<__half2*>(&u.y)); \
        m.x += (ES) * f0.x; m.y += (ES) * f0.y; \
        m.z += (ES) * f1.x; m.w += (ES) * f1.y; }
        ACC_TERM(e01.x, 0) ACC_TERM(e01.y, 1) ACC_TERM(e23.x, 2) ACC_TERM(e23.y, 3)
        ACC_TERM(e45.x, 4) ACC_TERM(e45.y, 5) ACC_TERM(e67.x, 6) ACC_TERM(e67.y, 7)
#undef ACC_TERM
        asm volatile("red.global.add.v4.f32 [%0], {%1,%2,%3,%4};"
                     :: "l"(dst + c * 4), "f"(m.x), "f"(m.y), "f"(m.z), "f"(m.w)
                     : "memory");
    }
}

// ---------------- mega kernel: pool + whole MLP (64 x 512, 3 gridbars) ----------------
// L1/L2 redundant per block; final reduce via last-block ticket (no bar 4).
// Also zeroes g_deg for the next call.
__global__ __launch_bounds__(512) void k_mega(
    const float* __restrict__ Wd1, const float* __restrict__ bd1,
    const float* __restrict__ Wd2, const float* __restrict__ bd2,
    const float* __restrict__ Wd3, const float* __restrict__ bd3,
    const float* __restrict__ Wd4, const float* __restrict__ bd4,
    const float* __restrict__ Wd5, const float* __restrict__ bd5,
    const float* __restrict__ Wd6, const float* __restrict__ bd6,
    float* __restrict__ out)
{
    __shared__ float w3s[256 * 12];
    __shared__ float w4s[768 * 8];
    __shared__ float w5s[512];
    __shared__ float a2[256];
    __shared__ float a3[768];
    __shared__ float v0[24];
    __shared__ float a1[96];
    __shared__ float poolacc[21][24];
    __shared__ float bd3s[12], bd4s[8];
    __shared__ float red8[8];

    int t = threadIdx.x;
    int b = blockIdx.x;
    int epoch = 0;

    // zero g_deg for next call's hist
    for (int i = b * 512 + t; i < N_NODES; i += MEGA_NB * 512) g_deg[i] = 0;

    for (int idx = t; idx < 256 * 12; idx += 512) {
        int i = idx / 12, j = idx % 12;
        w3s[idx] = Wd3[i * 768 + b * 12 + j];
    }
    for (int idx = t; idx < 768 * 8; idx += 512) {
        int i = idx / 8, j = idx % 8;
        w4s[idx] = Wd4[i * 512 + b * 8 + j];
    }
    if (t < 512) w5s[t] = Wd5[t * 64 + b];
    if (t < 12) bd3s[t] = bd3[b * 12 + t];
    if (t < 8)  bd4s[t] = bd4[b * 8 + t];
    float bd5b = bd5[b];
    float wd6b = Wd6[b];

    // phase P: pool partials (21 row-slots per block)
    {
        int c = t % 24, slot = t / 24;
        if (slot < 21) {
            float local = 0.0f;
            for (int r = b * 21 + slot; r < N_NODES; r += MEGA_NB * 21)
                local += fmaxf(__ldcg(&g_AGG3[r * 24 + c]), 0.0f);
            poolacc[slot][c] = local;
        }
        __syncthreads();
        if (t < 24) {
            float s = 0.0f;
#pragma unroll
            for (int k = 0; k < 21; k++) s += poolacc[k][t];
            g_poolpart[b * 24 + t] = s;
        }
    }
    gridbar(&g_barcnt, epoch, MEGA_NB);   // 1

    // phase A (redundant per block): pool reduce + L1 (24->96) + L2 (96->256)
    if (t < 24) {
        float s = 0.0f;
        for (int k = 0; k < MEGA_NB; k++) s += __ldcg(&g_poolpart[k * 24 + t]);
        v0[t] = s;
    }
    __syncthreads();
    if (t < 96) {
        float acc = bd1[t];
#pragma unroll
        for (int i = 0; i < 24; i++) acc += v0[i] * Wd1[i * 96 + t];
        a1[t] = fmaxf(acc, 0.0f);
    }
    __syncthreads();
    if (t < 256) {
        float acc = bd2[t];
#pragma unroll 8
        for (int i = 0; i < 96; i++) acc += a1[i] * Wd2[i * 256 + t];
        a2[t] = fmaxf(acc, 0.0f);
    }
    __syncthreads();

    // phase B: L3 256->768, 12 outputs per block (16 threads each)
    if (t < 192) {
        int jj = t >> 4, kk = t & 15;
        float acc = 0.0f;
#pragma unroll
        for (int r = 0; r < 16; r++) {
            int i = kk + 16 * r;
            acc += a2[i] * w3s[i * 12 + jj];
        }
#pragma unroll
        for (int off = 8; off >= 1; off >>= 1)
            acc += __shfl_down_sync(0xffffffffu, acc, off, 16);
        if (kk == 0) g_v2[b * 12 + jj] = fmaxf(acc + bd3s[jj], 0.0f);
    }
    gridbar(&g_barcnt, epoch, MEGA_NB);   // 2

    // phase C: L4 768->512, 8 outputs per block
    if (t < 256) {
#pragma unroll
        for (int k = 0; k < 3; k++) a3[t + k * 256] = __ldcg(&g_v2[t + k * 256]);
    }
    __syncthreads();
    if (t < 256) {
        int w = t >> 5, l = t & 31;
        float acc = 0.0f;
#pragma unroll
        for (int k = 0; k < 24; k++) {
            int i = l + 32 * k;
            acc += a3[i] * w4s[i * 8 + w];
        }
#pragma unroll
        for (int off = 16; off >= 1; off >>= 1)
            acc += __shfl_down_sync(0xffffffffu, acc, off);
        if (l == 0) g_v3[b * 8 + w] = fmaxf(acc + bd4s[w], 0.0f);
    }
    gridbar(&g_barcnt, epoch, MEGA_NB);   // 3

    // phase D: L5 512->64 (output b) * W6[b]; last-done block finishes.
    if (t < 256) {
        float acc = __ldcg(&g_v3[t]) * w5s[t] + __ldcg(&g_v3[t + 256]) * w5s[t + 256];
#pragma unroll
        for (int off = 16; off >= 1; off >>= 1)
            acc += __shfl_down_sync(0xffffffffu, acc, off);
        int w = t >> 5, l = t & 31;
        if (l == 0) red8[w] = acc;
    }
    __syncthreads();
    if (t == 0) {
        float s = 0.0f;
#pragma unroll
        for (int k = 0; k < 8; k++) s += red8[k];
        g_v3r[b] = fmaxf(s + bd5b, 0.0f) * wd6b;
        __threadfence();
        unsigned ticket = atomicAdd(&g_done, 1u);
        if (ticket == MEGA_NB - 1) {
            float tot = bd6[0];
#pragma unroll
            for (int k = 0; k < 64; k++) tot += __ldcg(&g_v3r[k]);
            out[0] = tot;
        }
    }
}

// ---------------- launcher ----------------
extern "C" void kernel_launch(void* const* d_in, const int* in_sizes, int n_in,
                              void* d_out, int out_size)
{
    const float* x    = (const float*)d_in[0];
    const int*   ei   = (const int*)d_in[1];
    const float* e    = (const float*)d_in[2];
    const float* We1  = (const float*)d_in[3];
    const float* be1  = (const float*)d_in[4];
    const float* root1= (const float*)d_in[5];
    const float* b1   = (const float*)d_in[6];
    const float* We2  = (const float*)d_in[7];
    const float* be2  = (const float*)d_in[8];
    const float* root2= (const float*)d_in[9];
    const float* b2   = (const float*)d_in[10];
    const float* We3  = (const float*)d_in[11];
    const float* be3  = (const float*)d_in[12];
    const float* root3= (const float*)d_in[13];
    const float* b3   = (const float*)d_in[14];
    const float* Wd1  = (const float*)d_in[15];
    const float* bd1  = (const float*)d_in[16];
    const float* Wd2  = (const float*)d_in[17];
    const float* bd2  = (const float*)d_in[18];
    const float* Wd3  = (const float*)d_in[19];
    const float* bd3  = (const float*)d_in[20];
    const float* Wd4  = (const float*)d_in[21];
    const float* bd4  = (const float*)d_in[22];
    const float* Wd5  = (const float*)d_in[23];
    const float* bd5  = (const float*)d_in[24];
    const float* Wd6  = (const float*)d_in[25];
    const float* bd6  = (const float*)d_in[26];

    const int2* ei2 = (const int2*)ei;
    const float4* e4 = (const float4*)e;

    const int ntile = (N_NODES + 255) / 256;                 // 79
    const int flat_grid = (N_EDGES + 255) / 256;             // 625
    const int edge_grid40 = (5 * N_EDGES + 255) / 256;       // 3125
    const int edge_grid24 = (3 * N_EDGES + 255) / 256;       // 1875

    k1_node1_hist<<<395 + 625, 256>>>(x, We1, be1, root1, b1, ei2);
    k_scanAB<<<40, 512>>>();
    k_scatter<<<flat_grid, 256>>>(ei2, e4);
    k_edge<1, 40, 5><<<edge_grid40, 256>>>();
    k_node<2, 40, 24, 5><<<dim3(ntile, 3), 256>>>(We2, be2, root2, b2);
    k_edge<2, 24, 3><<<edge_grid24, 256>>>();
    k_node<3, 24, 24, 5><<<dim3(ntile, 3), 256>>>(We3, be3, root3, b3);
    k_edge<3, 24, 3><<<edge_grid24, 256>>>();
    k_mega<<<MEGA_NB, 512>>>(Wd1, bd1, Wd2, bd2, Wd3, bd3, Wd4, bd4, Wd5, bd5,
                             Wd6, bd6, (float*)d_out);
}

// round 14
// speedup vs baseline: 1.9186x; 1.0191x over previous
#include <cuda_runtime.h>
#include <cuda_fp16.h>

// ---------------- problem constants ----------------
#define N_NODES 20000
#define N_EDGES 160000
#define MEGA_NB 64

// ---------------- device scratch (static; no allocs) ----------------
// P̄[n, s, o]: s=0..7 edge-weight slots, s=8 = R (unit coefficient). fp16.
__device__ __align__(16) __half g_Ph[N_NODES * 360];  // max 9*40 cols
__device__ __align__(16) float g_AGG1[N_NODES * 40];
__device__ __align__(16) float g_AGG2[N_NODES * 24];
__device__ __align__(16) float g_AGG3[N_NODES * 24];
__device__ int   g_deg[N_NODES];    // zero at load; re-zeroed by k_mega each call
__device__ int   g_cursor[N_NODES];
__device__ int   g_bsum[40];
__device__ __align__(8)  int2   g_srt[N_EDGES];       // (src, tgt) sorted by src
__device__ __align__(16) __half g_eperm_h[N_EDGES * 8];  // e payload fp16, src-sorted
__device__ float g_poolpart[MEGA_NB * 24];
__device__ __align__(16) float g_v2[768];
__device__ __align__(16) float g_v3[512];
__device__ float g_v3r[64];
__device__ unsigned g_barS;    // scanAB barrier
__device__ unsigned g_barcnt;  // mega barrier
__device__ unsigned g_done;    // mega last-block ticket

// ---------------- helpers ----------------
__device__ __forceinline__ void ffma2(unsigned long long& d, unsigned long long a,
                                      unsigned long long b) {
    asm("fma.rn.f32x2 %0, %1, %2, %0;" : "+l"(d) : "l"(a), "l"(b));
}
__device__ __forceinline__ unsigned long long packf2(float x) {
    unsigned long long r;
    asm("mov.b64 %0, {%1, %1};" : "=l"(r) : "f"(x));
    return r;
}
__device__ __forceinline__ float2 unpackf2(unsigned long long v) {
    float2 f;
    asm("mov.b64 {%0, %1}, %2;" : "=f"(f.x), "=f"(f.y) : "l"(v));
    return f;
}
// unpack 8 fp16 (uint4) -> two float4
__device__ __forceinline__ void h8_to_f8(uint4 u, float4& a, float4& b) {
    float2 f0 = __half22float2(*reinterpret_cast<__half2*>(&u.x));
    float2 f1 = __half22float2(*reinterpret_cast<__half2*>(&u.y));
    float2 f2 = __half22float2(*reinterpret_cast<__half2*>(&u.z));
    float2 f3 = __half22float2(*reinterpret_cast<__half2*>(&u.w));
    a = make_float4(f0.x, f0.y, f1.x, f1.y);
    b = make_float4(f2.x, f2.y, f3.x, f3.y);
}
__device__ __forceinline__ void gridbar(unsigned* cnt, int& epoch, int nb) {
    __threadfence();
    __syncthreads();
    epoch++;
    if (threadIdx.x == 0) {
        atomicAdd(cnt, 1u);
        unsigned target = (unsigned)epoch * (unsigned)nb;
        while (*((volatile unsigned*)cnt) < target) __nanosleep(20);
    }
    __syncthreads();
}

// ---------------- k1: node1 (blocks 0..394) || hist (blocks 395..1019) ----------------
// node1: cols [0,360) P̄(fp16, incl. R at s=8), [360,400) AGG1(+bias).
__global__ __launch_bounds__(256) void k1_node1_hist(
    const float* __restrict__ xin,
    const float* __restrict__ We, const float* __restrict__ be,
    const float* __restrict__ root, const float* __restrict__ bias,
    const int2* __restrict__ ei)
{
    constexpr int FI = 16, FO = 40, CC = 5;
    constexpr int CC16 = CC * 16;
    __shared__ __align__(16) float Wsh[FI * CC16];
    __shared__ float bsh[FO];
    int t = threadIdx.x;
    int b = blockIdx.x;

    if (b >= 395) {   // histogram blocks (full 160k-thread parallelism)
        int i = (b - 395) * 256 + t;
        if (i < N_EDGES) atomicAdd(&g_deg[ei[i].x], 1);
        return;
    }

    int bx = b % 79;        // node tile
    int by = b / 79;        // col chunk
    int cg0 = by * CC;
    int colbase = cg0 * 16;

    if (b == 0 && t == 0) { g_barS = 0u; g_barcnt = 0u; g_done = 0u; }

    for (int idx = t; idx < FI * CC16; idx += 256) {
        int f = idx / CC16, cl = idx % CC16;
        int c = colbase + cl;
        float w;
        if (c < 8 * FO) {
            int s = c / FO, o = c % FO;
            w = We[s * (FI * FO) + f * FO + o];
        } else if (c < 9 * FO) {
            int o = c - 8 * FO;
            w = be[f * FO + o];
        } else {
            int o = c - 9 * FO;
            w = root[f * FO + o];
        }
        Wsh[idx] = w;
    }
    for (int idx = t; idx < FO; idx += 256) bsh[idx] = bias[idx];
    __syncthreads();

    int node = bx * 256 + t;
    if (node >= N_NODES) return;

    float h[FI];
    const float4* hv = reinterpret_cast<const float4*>(xin + (size_t)node * FI);
#pragma unroll
    for (int f4 = 0; f4 < FI / 4; f4++) {
        float4 a = hv[f4];
        h[4*f4+0]=a.x; h[4*f4+1]=a.y; h[4*f4+2]=a.z; h[4*f4+3]=a.w;
    }

    const ulonglong2* Wv = reinterpret_cast<const ulonglong2*>(Wsh);
    uint4* Pv = reinterpret_cast<uint4*>(g_Ph) + (size_t)node * (9 * FO / 8);
    float4* Av = reinterpret_cast<float4*>(g_AGG1) + (size_t)node * (FO / 4);

#pragma unroll
    for (int cg = 0; cg < CC; cg++) {
        unsigned long long acc[8];
#pragma unroll
        for (int k = 0; k < 8; k++) acc[k] = 0ull;
#pragma unroll
        for (int f = 0; f < FI; f++) {
            const ulonglong2* wrow = Wv + f * (CC * 4) + cg * 4;
            ulonglong2 wA = wrow[0], wB = wrow[1], wC = wrow[2], wD = wrow[3];
            unsigned long long ha = packf2(h[f]);
            ffma2(acc[0], ha, wA.x); ffma2(acc[1], ha, wA.y);
            ffma2(acc[2], ha, wB.x); ffma2(acc[3], ha, wB.y);
            ffma2(acc[4], ha, wC.x); ffma2(acc[5], ha, wC.y);
            ffma2(acc[6], ha, wD.x); ffma2(acc[7], ha, wD.y);
        }
#pragma unroll
        for (int q2 = 0; q2 < 2; q2++) {   // 8 cols per store group
            int cb = (cg0 + cg) * 16 + q2 * 8;
            float2 a0 = unpackf2(acc[4*q2+0]), a1 = unpackf2(acc[4*q2+1]);
            float2 a2 = unpackf2(acc[4*q2+2]), a3 = unpackf2(acc[4*q2+3]);
            if (cb < 9 * FO) {
                union { __half2 h2[4]; uint4 u; } pk;
                pk.h2[0] = __floats2half2_rn(a0.x, a0.y);
                pk.h2[1] = __floats2half2_rn(a1.x, a1.y);
                pk.h2[2] = __floats2half2_rn(a2.x, a2.y);
                pk.h2[3] = __floats2half2_rn(a3.x, a3.y);
                Pv[cb / 8] = pk.u;
            } else {
                int o = cb - 9 * FO;
                float4 va = make_float4(a0.x + bsh[o],   a0.y + bsh[o+1],
                                        a1.x + bsh[o+2], a1.y + bsh[o+3]);
                float4 vb = make_float4(a2.x + bsh[o+4], a2.y + bsh[o+5],
                                        a3.x + bsh[o+6], a3.y + bsh[o+7]);
                Av[o / 4]     = va;
                Av[o / 4 + 1] = vb;
            }
        }
    }
}

// ---------------- k2: fused two-level scan (40 blocks x 512, 1 gridbar) ----------------
__global__ __launch_bounds__(512) void k_scanAB()
{
    __shared__ int wred[16];
    __shared__ int bs[40];
    __shared__ int base;
    __shared__ int wsum[16];
    int t = threadIdx.x;
    int lane = t & 31, w = t >> 5;
    int b = blockIdx.x;
    int epoch = 0;

    int idx = b * 500 + t;
    int d = (t < 500 && idx < N_NODES) ? g_deg[idx] : 0;

    {
        int s = d;
#pragma unroll
        for (int off = 16; off >= 1; off >>= 1)
            s += __shfl_down_sync(0xffffffffu, s, off);
        if (lane == 0) wred[w] = s;
        __syncthreads();
        if (w == 0) {
            int v = (lane < 16) ? wred[lane] : 0;
#pragma unroll
            for (int off = 8; off >= 1; off >>= 1)
                v += __shfl_down_sync(0xffffffffu, v, off);
            if (lane == 0) g_bsum[b] = v;
        }
    }
    gridbar(&g_barS, epoch, 40);

    if (t < 40) bs[t] = g_bsum[t];
    __syncthreads();
    if (t == 0) {
        int s = 0;
#pragma unroll
        for (int i = 0; i < 40; i++) if (i < b) s += bs[i];
        base = s;
    }
    int sc = d;
#pragma unroll
    for (int off = 1; off < 32; off <<= 1) {
        int n = __shfl_up_sync(0xffffffffu, sc, off);
        if (lane >= off) sc += n;
    }
    if (lane == 31) wsum[w] = sc;
    __syncthreads();
    if (w == 0) {
        int v = (lane < 16) ? wsum[lane] : 0;
#pragma unroll
        for (int off = 1; off < 16; off <<= 1) {
            int n = __shfl_up_sync(0xffffffffu, v, off);
            if (lane >= off) v += n;
        }
        if (lane < 16) wsum[lane] = v;
    }
    __syncthreads();
    int wbase = (w == 0) ? 0 : wsum[w - 1];
    if (t < 500 && idx < N_NODES) g_cursor[idx] = base + wbase + sc - d;
}

// ---------------- k3: scatter (1 edge/thread; e converted to fp16) ----------------
__global__ void k_scatter(const int2* __restrict__ ei, const float4* __restrict__ e4) {
    int i = blockIdx.x * blockDim.x + threadIdx.x;
    if (i < N_EDGES) {
        int2 st = ei[i];
        float4 a = e4[2 * i], b = e4[2 * i + 1];
        union { __half2 h2[4]; uint4 u; } pk;
        pk.h2[0] = __floats2half2_rn(a.x, a.y);
        pk.h2[1] = __floats2half2_rn(a.z, a.w);
        pk.h2[2] = __floats2half2_rn(b.x, b.y);
        pk.h2[3] = __floats2half2_rn(b.z, b.w);
        int p = atomicAdd(&g_cursor[st.x], 1);
        g_srt[p] = st;
        reinterpret_cast<uint4*>(g_eperm_h)[p] = pk.u;
    }
}

// ---------------- node kernel (layers 2/3) ----------------
template <int LAYER, int FI, int FO, int CC>
__global__ __launch_bounds__(256) void k_node(
    const float* __restrict__ We, const float* __restrict__ be,
    const float* __restrict__ root, const float* __restrict__ bias)
{
    constexpr int CC16 = CC * 16;
    __shared__ __align__(16) float Wsh[FI * CC16];
    __shared__ float bsh[FO];
    int t = threadIdx.x;
    int cg0 = blockIdx.y * CC;
    int colbase = cg0 * 16;

    for (int idx = t; idx < FI * CC16; idx += 256) {
        int f = idx / CC16, cl = idx % CC16;
        int c = colbase + cl;
        float w;
        if (c < 8 * FO) {
            int s = c / FO, o = c % FO;
            w = We[s * (FI * FO) + f * FO + o];
        } else if (c < 9 * FO) {
            int o = c - 8 * FO;
            w = be[f * FO + o];
        } else {
            int o = c - 9 * FO;
            w = root[f * FO + o];
        }
        Wsh[idx] = w;
    }
    for (int idx = t; idx < FO; idx += 256) bsh[idx] = bias[idx];
    __syncthreads();

    int node = blockIdx.x * 256 + t;
    if (node >= N_NODES) return;

    const float* hin = (LAYER == 2) ? g_AGG1 : g_AGG2;
    float* AGG       = (LAYER == 2) ? g_AGG2 : g_AGG3;

    float h[FI];
    const float4* hv = reinterpret_cast<const float4*>(hin + (size_t)node * FI);
#pragma unroll
    for (int f4 = 0; f4 < FI / 4; f4++) {
        float4 a = hv[f4];
        a.x = fmaxf(a.x, 0.f); a.y = fmaxf(a.y, 0.f);
        a.z = fmaxf(a.z, 0.f); a.w = fmaxf(a.w, 0.f);
        h[4*f4+0]=a.x; h[4*f4+1]=a.y; h[4*f4+2]=a.z; h[4*f4+3]=a.w;
    }

    const ulonglong2* Wv = reinterpret_cast<const ulonglong2*>(Wsh);
    uint4* Pv = reinterpret_cast<uint4*>(g_Ph) + (size_t)node * (9 * FO / 8);
    float4* Av = reinterpret_cast<float4*>(AGG) + (size_t)node * (FO / 4);

#pragma unroll
    for (int cg = 0; cg < CC; cg++) {
        unsigned long long acc[8];
#pragma unroll
        for (int k = 0; k < 8; k++) acc[k] = 0ull;
#pragma unroll
        for (int f = 0; f < FI; f++) {
            const ulonglong2* wrow = Wv + f * (CC * 4) + cg * 4;
            ulonglong2 wA = wrow[0], wB = wrow[1], wC = wrow[2], wD = wrow[3];
            unsigned long long ha = packf2(h[f]);
            ffma2(acc[0], ha, wA.x); ffma2(acc[1], ha, wA.y);
            ffma2(acc[2], ha, wB.x); ffma2(acc[3], ha, wB.y);
            ffma2(acc[4], ha, wC.x); ffma2(acc[5], ha, wC.y);
            ffma2(acc[6], ha, wD.x); ffma2(acc[7], ha, wD.y);
        }
#pragma unroll
        for (int q2 = 0; q2 < 2; q2++) {
            int cb = (cg0 + cg) * 16 + q2 * 8;
            float2 a0 = unpackf2(acc[4*q2+0]), a1 = unpackf2(acc[4*q2+1]);
            float2 a2 = unpackf2(acc[4*q2+2]), a3 = unpackf2(acc[4*q2+3]);
            if (cb < 9 * FO) {
                union { __half2 h2[4]; uint4 u; } pk;
                pk.h2[0] = __floats2half2_rn(a0.x, a0.y);
                pk.h2[1] = __floats2half2_rn(a1.x, a1.y);
                pk.h2[2] = __floats2half2_rn(a2.x, a2.y);
                pk.h2[3] = __floats2half2_rn(a3.x, a3.y);
                Pv[cb / 8] = pk.u;
            } else {
                int o = cb - 9 * FO;
                float4 va = make_float4(a0.x + bsh[o],   a0.y + bsh[o+1],
                                        a1.x + bsh[o+2], a1.y + bsh[o+3]);
                float4 vb = make_float4(a2.x + bsh[o+4], a2.y + bsh[o+5],
                                        a3.x + bsh[o+6], a3.y + bsh[o+7]);
                Av[o / 4]     = va;
                Av[o / 4 + 1] = vb;
            }
        }
    }
}

// ---------------- edge kernel ----------------
// TPE threads per edge; each thread owns one aligned 8-column uint4 span per slot.
// msg = P̄[8] + Σ_s e_s·P̄[s]; P̄ and e fp16; two red.v4 per thread.
template <int LAYER, int FO, int TPE>
__global__ __launch_bounds__(256) void k_edge()
{
    constexpr int FO8 = FO / 8;    // uint4 per slot (== TPE)
    int gid = blockIdx.x * 256 + threadIdx.x;
    int edge = gid / TPE;
    if (edge >= N_EDGES) return;
    int part = gid - edge * TPE;

    int2 st = g_srt[edge];
    uint4 eu = reinterpret_cast<const uint4*>(g_eperm_h)[edge];
    float2 e01 = __half22float2(*reinterpret_cast<__half2*>(&eu.x));
    float2 e23 = __half22float2(*reinterpret_cast<__half2*>(&eu.y));
    float2 e45 = __half22float2(*reinterpret_cast<__half2*>(&eu.z));
    float2 e67 = __half22float2(*reinterpret_cast<__half2*>(&eu.w));

    const uint4* P = reinterpret_cast<const uint4*>(g_Ph)
                     + (size_t)st.x * (9 * FO8) + part;
    float* AGG;
    if (LAYER == 1)      AGG = g_AGG1;
    else if (LAYER == 2) AGG = g_AGG2;
    else                 AGG = g_AGG3;
    float* dst = AGG + (size_t)st.y * FO + part * 8;

    float4 m0, m1;
    h8_to_f8(P[8 * FO8], m0, m1);   // R term (s=8, unit coefficient)
#define ACC_TERM(ES, SI) { \
    float4 p0, p1; \
    h8_to_f8(P[(SI) * FO8], p0, p1); \
    m0.x += (ES) * p0.x; m0.y += (ES) * p0.y; m0.z += (ES) * p0.z; m0.w += (ES) * p0.w; \
    m1.x += (ES) * p1.x; m1.y += (ES) * p1.y; m1.z += (ES) * p1.z; m1.w += (ES) * p1.w; }
    ACC_TERM(e01.x, 0) ACC_TERM(e01.y, 1) ACC_TERM(e23.x, 2) ACC_TERM(e23.y, 3)
    ACC_TERM(e45.x, 4) ACC_TERM(e45.y, 5) ACC_TERM(e67.x, 6) ACC_TERM(e67.y, 7)
#undef ACC_TERM
    asm volatile("red.global.add.v4.f32 [%0], {%1,%2,%3,%4};"
                 :: "l"(dst), "f"(m0.x), "f"(m0.y), "f"(m0.z), "f"(m0.w) : "memory");
    asm volatile("red.global.add.v4.f32 [%0], {%1,%2,%3,%4};"
                 :: "l"(dst + 4), "f"(m1.x), "f"(m1.y), "f"(m1.z), "f"(m1.w) : "memory");
}

// ---------------- mega kernel: pool + whole MLP (64 x 512, 3 gridbars) ----------------
__global__ __launch_bounds__(512) void k_mega(
    const float* __restrict__ Wd1, const float* __restrict__ bd1,
    const float* __restrict__ Wd2, const float* __restrict__ bd2,
    const float* __restrict__ Wd3, const float* __restrict__ bd3,
    const float* __restrict__ Wd4, const float* __restrict__ bd4,
    const float* __restrict__ Wd5, const float* __restrict__ bd5,
    const float* __restrict__ Wd6, const float* __restrict__ bd6,
    float* __restrict__ out)
{
    __shared__ float w3s[256 * 12];
    __shared__ float w4s[768 * 8];
    __shared__ float w5s[512];
    __shared__ float a2[256];
    __shared__ float a3[768];
    __shared__ float v0[24];
    __shared__ float a1[96];
    __shared__ float poolacc[21][24];
    __shared__ float bd3s[12], bd4s[8];
    __shared__ float red8[8];

    int t = threadIdx.x;
    int b = blockIdx.x;
    int epoch = 0;

    // zero g_deg for next call's hist
    for (int i = b * 512 + t; i < N_NODES; i += MEGA_NB * 512) g_deg[i] = 0;

    for (int idx = t; idx < 256 * 12; idx += 512) {
        int i = idx / 12, j = idx % 12;
        w3s[idx] = Wd3[i * 768 + b * 12 + j];
    }
    for (int idx = t; idx < 768 * 8; idx += 512) {
        int i = idx / 8, j = idx % 8;
        w4s[idx] = Wd4[i * 512 + b * 8 + j];
    }
    if (t < 512) w5s[t] = Wd5[t * 64 + b];
    if (t < 12) bd3s[t] = bd3[b * 12 + t];
    if (t < 8)  bd4s[t] = bd4[b * 8 + t];
    float bd5b = bd5[b];
    float wd6b = Wd6[b];

    // phase P: pool partials (21 row-slots per block)
    {
        int c = t % 24, slot = t / 24;
        if (slot < 21) {
            float local = 0.0f;
            for (int r = b * 21 + slot; r < N_NODES; r += MEGA_NB * 21)
                local += fmaxf(__ldcg(&g_AGG3[r * 24 + c]), 0.0f);
            poolacc[slot][c] = local;
        }
        __syncthreads();
        if (t < 24) {
            float s = 0.0f;
#pragma unroll
            for (int k = 0; k < 21; k++) s += poolacc[k][t];
            g_poolpart[b * 24 + t] = s;
        }
    }
    gridbar(&g_barcnt, epoch, MEGA_NB);   // 1

    // phase A (redundant per block): pool reduce + L1 (24->96) + L2 (96->256)
    if (t < 24) {
        float s = 0.0f;
        for (int k = 0; k < MEGA_NB; k++) s += __ldcg(&g_poolpart[k * 24 + t]);
        v0[t] = s;
    }
    __syncthreads();
    if (t < 96) {
        float acc = bd1[t];
#pragma unroll
        for (int i = 0; i < 24; i++) acc += v0[i] * Wd1[i * 96 + t];
        a1[t] = fmaxf(acc, 0.0f);
    }
    __syncthreads();
    if (t < 256) {
        float acc = bd2[t];
#pragma unroll 8
        for (int i = 0; i < 96; i++) acc += a1[i] * Wd2[i * 256 + t];
        a2[t] = fmaxf(acc, 0.0f);
    }
    __syncthreads();

    // phase B: L3 256->768, 12 outputs per block (16 threads each)
    if (t < 192) {
        int jj = t >> 4, kk = t & 15;
        float acc = 0.0f;
#pragma unroll
        for (int r = 0; r < 16; r++) {
            int i = kk + 16 * r;
            acc += a2[i] * w3s[i * 12 + jj];
        }
#pragma unroll
        for (int off = 8; off >= 1; off >>= 1)
            acc += __shfl_down_sync(0xffffffffu, acc, off, 16);
        if (kk == 0) g_v2[b * 12 + jj] = fmaxf(acc + bd3s[jj], 0.0f);
    }
    gridbar(&g_barcnt, epoch, MEGA_NB);   // 2

    // phase C: L4 768->512, 8 outputs per block
    if (t < 256) {
#pragma unroll
        for (int k = 0; k < 3; k++) a3[t + k * 256] = __ldcg(&g_v2[t + k * 256]);
    }
    __syncthreads();
    if (t < 256) {
        int w = t >> 5, l = t & 31;
        float acc = 0.0f;
#pragma unroll
        for (int k = 0; k < 24; k++) {
            int i = l + 32 * k;
            acc += a3[i] * w4s[i * 8 + w];
        }
#pragma unroll
        for (int off = 16; off >= 1; off >>= 1)
            acc += __shfl_down_sync(0xffffffffu, acc, off);
        if (l == 0) g_v3[b * 8 + w] = fmaxf(acc + bd4s[w], 0.0f);
    }
    gridbar(&g_barcnt, epoch, MEGA_NB);   // 3

    // phase D: L5 512->64 (output b) * W6[b]; last-done block finishes.
    if (t < 256) {
        float acc = __ldcg(&g_v3[t]) * w5s[t] + __ldcg(&g_v3[t + 256]) * w5s[t + 256];
#pragma unroll
        for (int off = 16; off >= 1; off >>= 1)
            acc += __shfl_down_sync(0xffffffffu, acc, off);
        int w = t >> 5, l = t & 31;
        if (l == 0) red8[w] = acc;
    }
    __syncthreads();
    if (t == 0) {
        float s = 0.0f;
#pragma unroll
        for (int k = 0; k < 8; k++) s += red8[k];
        g_v3r[b] = fmaxf(s + bd5b, 0.0f) * wd6b;
        __threadfence();
        unsigned ticket = atomicAdd(&g_done, 1u);
        if (ticket == MEGA_NB - 1) {
            float tot = bd6[0];
#pragma unroll
            for (int k = 0; k < 64; k++) tot += __ldcg(&g_v3r[k]);
            out[0] = tot;
        }
    }
}

// ---------------- launcher ----------------
extern "C" void kernel_launch(void* const* d_in, const int* in_sizes, int n_in,
                              void* d_out, int out_size)
{
    const float* x    = (const float*)d_in[0];
    const int*   ei   = (const int*)d_in[1];
    const float* e    = (const float*)d_in[2];
    const float* We1  = (const float*)d_in[3];
    const float* be1  = (const float*)d_in[4];
    const float* root1= (const float*)d_in[5];
    const float* b1   = (const float*)d_in[6];
    const float* We2  = (const float*)d_in[7];
    const float* be2  = (const float*)d_in[8];
    const float* root2= (const float*)d_in[9];
    const float* b2   = (const float*)d_in[10];
    const float* We3  = (const float*)d_in[11];
    const float* be3  = (const float*)d_in[12];
    const float* root3= (const float*)d_in[13];
    const float* b3   = (const float*)d_in[14];
    const float* Wd1  = (const float*)d_in[15];
    const float* bd1  = (const float*)d_in[16];
    const float* Wd2  = (const float*)d_in[17];
    const float* bd2  = (const float*)d_in[18];
    const float* Wd3  = (const float*)d_in[19];
    const float* bd3  = (const float*)d_in[20];
    const float* Wd4  = (const float*)d_in[21];
    const float* bd4  = (const float*)d_in[22];
    const float* Wd5  = (const float*)d_in[23];
    const float* bd5  = (const float*)d_in[24];
    const float* Wd6  = (const float*)d_in[25];
    const float* bd6  = (const float*)d_in[26];

    const int2* ei2 = (const int2*)ei;
    const float4* e4 = (const float4*)e;

    const int ntile = (N_NODES + 255) / 256;                 // 79
    const int flat_grid = (N_EDGES + 255) / 256;             // 625
    const int edge_grid40 = (5 * N_EDGES + 255) / 256;       // 3125
    const int edge_grid24 = (3 * N_EDGES + 255) / 256;       // 1875

    k1_node1_hist<<<395 + 625, 256>>>(x, We1, be1, root1, b1, ei2);
    k_scanAB<<<40, 512>>>();
    k_scatter<<<flat_grid, 256>>>(ei2, e4);
    k_edge<1, 40, 5><<<edge_grid40, 256>>>();
    k_node<2, 40, 24, 5><<<dim3(ntile, 3), 256>>>(We2, be2, root2, b2);
    k_edge<2, 24, 3><<<edge_grid24, 256>>>();
    k_node<3, 24, 24, 5><<<dim3(ntile, 3), 256>>>(We3, be3, root3, b3);
    k_edge<3, 24, 3><<<edge_grid24, 256>>>();
    k_mega<<<MEGA_NB, 512>>>(Wd1, bd1, Wd2, bd2, Wd3, bd3, Wd4, bd4, Wd5, bd5,
                             Wd6, bd6, (float*)d_out);
}